// round 3
// baseline (speedup 1.0000x reference)
#include <cuda_runtime.h>

#define N_NODES 50000
#define N_EDGES 800000
#define EE (N_EDGES + N_NODES)   // edges + self loops = 850000
#define NG 64
#define NCLS 10
#define NEG_SLOPE 0.2f
#define EPS 1e-16f

// ---------------- scratch (static device globals; no runtime alloc) -------------
__device__ __align__(16) float g_bufA[N_NODES * 256];   // gemm output (h) per layer
__device__ __align__(16) float g_bufB[N_NODES * 256];   // aggregation output per layer
__device__ __align__(16) float g_as[N_NODES * 4];
__device__ __align__(16) float g_ad[N_NODES * 4];
__device__ __align__(16) float g_m[N_NODES * 4];
__device__ __align__(16) float g_den[N_NODES * 4];
__device__ __align__(16) float g_e[EE * 4];
__device__ __align__(16) int   g_src[EE];
__device__ __align__(16) int   g_dst[EE];
__device__ __align__(16) int   g_batch[N_NODES];
__device__ __align__(16) float g_pool[NG * 64 + NG];    // sums [64,64] then counts [64]
__device__ int g_flags[2];  // [0]=edge_index is int64, [1]=batch is int64

// ---------------- helpers -------------------------------------------------------
__device__ __forceinline__ void atomicMaxF(float* addr, float v) {
    if (v >= 0.0f) atomicMax((int*)addr, __float_as_int(v));
    else           atomicMin((unsigned int*)addr, __float_as_uint(v));
}

__device__ __forceinline__ void red_add_v4(float* addr, float a, float b, float c, float d) {
    asm volatile("red.global.add.v4.f32 [%0], {%1,%2,%3,%4};"
                 :: "l"(addr), "f"(a), "f"(b), "f"(c), "f"(d) : "memory");
}
__device__ __forceinline__ void red_add_v2(float* addr, float a, float b) {
    asm volatile("red.global.add.v2.f32 [%0], {%1,%2};"
                 :: "l"(addr), "f"(a), "f"(b) : "memory");
}

__device__ __forceinline__ float lrelu(float v) { return v >= 0.0f ? v : NEG_SLOPE * v; }

// ---------------- dtype detection -----------------------------------------------
// JAX default config downgrades requested int64 to int32; detect which one the
// harness actually gave us. Interpreting genuine int32 data as int64 fuses two
// values into lo + hi*2^32 which is wildly out of range. All probe reads stay
// within the int32-sized buffer, so this is safe for either dtype.
__global__ void detect_dtypes(const void* ei, const void* bat) {
    if (threadIdx.x != 0 || blockIdx.x != 0) return;
    const long long* e64 = (const long long*)ei;
    int ok = 1;
    for (int i = 0; i < 8; i++) {
        long long v = e64[i];                       // always in-bounds
        if (v < 0 || v >= N_NODES) ok = 0;
    }
    g_flags[0] = ok;
    const long long* b64 = (const long long*)bat;
    int okb = 1;
    for (int i = 0; i < 8; i++) {
        long long v = b64[N_NODES / 2 - 1 - i];     // probe near end (values ~63, not 0)
        if (v < 0 || v >= NG) okb = 0;
    }
    g_flags[1] = okb;
}

// ---------------- edge list build (append self loops) ---------------------------
__global__ void build_edges(const void* ei, int* __restrict__ src, int* __restrict__ dst) {
    int i = blockIdx.x * blockDim.x + threadIdx.x;
    if (i >= EE) return;
    if (i < N_EDGES) {
        if (g_flags[0]) {
            const long long* e = (const long long*)ei;
            src[i] = (int)e[i];
            dst[i] = (int)e[N_EDGES + i];
        } else {
            const int* e = (const int*)ei;
            src[i] = e[i];
            dst[i] = e[N_EDGES + i];
        }
    } else {
        int n = i - N_EDGES;
        src[i] = n;
        dst[i] = n;
    }
}

__global__ void conv_batch(const void* bat, int* __restrict__ out) {
    int i = blockIdx.x * blockDim.x + threadIdx.x;
    if (i >= N_NODES) return;
    if (g_flags[1]) out[i] = (int)((const long long*)bat)[i];
    else            out[i] = ((const int*)bat)[i];
}

// ---------------- SGEMM: C[M,N] = A[M,K] @ B[K,N]  (BM=BN=64, BK=16, 4x4/thr) ---
__global__ void sgemm(const float* __restrict__ A, const float* __restrict__ B,
                      float* __restrict__ C, int M, int N, int K) {
    __shared__ float As[16][64];
    __shared__ float Bs[16][64];
    int tid = threadIdx.x;
    int tx = tid & 15, ty = tid >> 4;
    int m0 = blockIdx.y * 64, n0 = blockIdx.x * 64;
    float acc[4][4] = {};
    int ar = tid >> 2, ac = (tid & 3) << 2;     // A tile: 64 rows x 16 cols
    int br = tid >> 4, bc = (tid & 15) << 2;    // B tile: 16 rows x 64 cols

    for (int k0 = 0; k0 < K; k0 += 16) {
        float4 av = make_float4(0.f, 0.f, 0.f, 0.f);
        if (m0 + ar < M)
            av = *(const float4*)(A + (size_t)(m0 + ar) * K + k0 + ac);
        As[ac + 0][ar] = av.x; As[ac + 1][ar] = av.y;
        As[ac + 2][ar] = av.z; As[ac + 3][ar] = av.w;
        float4 bv = *(const float4*)(B + (size_t)(k0 + br) * N + n0 + bc);
        *(float4*)&Bs[br][bc] = bv;
        __syncthreads();
#pragma unroll
        for (int k = 0; k < 16; k++) {
            float a[4], b[4];
#pragma unroll
            for (int i = 0; i < 4; i++) a[i] = As[k][ty * 4 + i];
#pragma unroll
            for (int j = 0; j < 4; j++) b[j] = Bs[k][tx * 4 + j];
#pragma unroll
            for (int i = 0; i < 4; i++)
#pragma unroll
                for (int j = 0; j < 4; j++) acc[i][j] += a[i] * b[j];
        }
        __syncthreads();
    }
#pragma unroll
    for (int i = 0; i < 4; i++) {
        int row = m0 + ty * 4 + i;
        if (row < M) {
#pragma unroll
            for (int j = 0; j < 4; j++)
                C[(size_t)row * N + n0 + tx * 4 + j] = acc[i][j];
        }
    }
}

// ---------------- per-node prep: alpha_src/dst dots, init m/den, zero out -------
// H=4, C=64 (row = 256 floats). One warp per node.
__global__ void node_prep4(const float* __restrict__ h, const float* __restrict__ a_src,
                           const float* __restrict__ a_dst, float* __restrict__ as,
                           float* __restrict__ ad, float* __restrict__ m,
                           float* __restrict__ den, float* __restrict__ outz) {
    int warp = (blockIdx.x * blockDim.x + threadIdx.x) >> 5;
    int lane = threadIdx.x & 31;
    if (warp >= N_NODES) return;
    const float4* hr = (const float4*)(h + (size_t)warp * 256);
    const float4* sr = (const float4*)a_src;
    const float4* dr = (const float4*)a_dst;
    float4 h0 = hr[lane * 2], h1 = hr[lane * 2 + 1];
    float4 s0 = sr[lane * 2], s1 = sr[lane * 2 + 1];
    float4 d0 = dr[lane * 2], d1 = dr[lane * 2 + 1];
    float ps = h0.x * s0.x + h0.y * s0.y + h0.z * s0.z + h0.w * s0.w +
               h1.x * s1.x + h1.y * s1.y + h1.z * s1.z + h1.w * s1.w;
    float pd = h0.x * d0.x + h0.y * d0.y + h0.z * d0.z + h0.w * d0.w +
               h1.x * d1.x + h1.y * d1.y + h1.z * d1.z + h1.w * d1.w;
    // reduce within each group of 8 lanes (one head per group)
#pragma unroll
    for (int o = 4; o >= 1; o >>= 1) {
        ps += __shfl_down_sync(0xffffffffu, ps, o, 8);
        pd += __shfl_down_sync(0xffffffffu, pd, o, 8);
    }
    if ((lane & 7) == 0) {
        int hd = lane >> 3;
        as[warp * 4 + hd] = ps;
        ad[warp * 4 + hd] = pd;
        m[warp * 4 + hd] = -INFINITY;
        den[warp * 4 + hd] = 0.0f;
    }
    float4 z = make_float4(0.f, 0.f, 0.f, 0.f);
    float4* orow = (float4*)(outz + (size_t)warp * 256);
    orow[lane * 2] = z;
    orow[lane * 2 + 1] = z;
}

// H=1, C=64
__global__ void node_prep1(const float* __restrict__ h, const float* __restrict__ a_src,
                           const float* __restrict__ a_dst, float* __restrict__ as,
                           float* __restrict__ ad, float* __restrict__ m,
                           float* __restrict__ den, float* __restrict__ outz) {
    int warp = (blockIdx.x * blockDim.x + threadIdx.x) >> 5;
    int lane = threadIdx.x & 31;
    if (warp >= N_NODES) return;
    float2 hv = ((const float2*)(h + (size_t)warp * 64))[lane];
    float2 sv = ((const float2*)a_src)[lane];
    float2 dv = ((const float2*)a_dst)[lane];
    float ps = hv.x * sv.x + hv.y * sv.y;
    float pd = hv.x * dv.x + hv.y * dv.y;
#pragma unroll
    for (int o = 16; o >= 1; o >>= 1) {
        ps += __shfl_down_sync(0xffffffffu, ps, o);
        pd += __shfl_down_sync(0xffffffffu, pd, o);
    }
    if (lane == 0) {
        as[warp] = ps;
        ad[warp] = pd;
        m[warp] = -INFINITY;
        den[warp] = 0.0f;
    }
    ((float2*)(outz + (size_t)warp * 64))[lane] = make_float2(0.f, 0.f);
}

// ---------------- edge pass A: e = leaky(as[src]+ad[dst]); segment max ----------
__global__ void edge_max4(const float* __restrict__ as, const float* __restrict__ ad,
                          const int* __restrict__ src, const int* __restrict__ dst,
                          float* __restrict__ eb, float* __restrict__ m) {
    int i = blockIdx.x * blockDim.x + threadIdx.x;
    if (i >= EE) return;
    int s = src[i], d = dst[i];
    float4 a = ((const float4*)as)[s];
    float4 b = ((const float4*)ad)[d];
    float4 e;
    e.x = lrelu(a.x + b.x); e.y = lrelu(a.y + b.y);
    e.z = lrelu(a.z + b.z); e.w = lrelu(a.w + b.w);
    ((float4*)eb)[i] = e;
    atomicMaxF(&m[d * 4 + 0], e.x);
    atomicMaxF(&m[d * 4 + 1], e.y);
    atomicMaxF(&m[d * 4 + 2], e.z);
    atomicMaxF(&m[d * 4 + 3], e.w);
}

__global__ void edge_max1(const float* __restrict__ as, const float* __restrict__ ad,
                          const int* __restrict__ src, const int* __restrict__ dst,
                          float* __restrict__ eb, float* __restrict__ m) {
    int i = blockIdx.x * blockDim.x + threadIdx.x;
    if (i >= EE) return;
    int s = src[i], d = dst[i];
    float e = lrelu(as[s] + ad[d]);
    eb[i] = e;
    atomicMaxF(&m[d], e);
}

// ---------------- edge pass B: ex = exp(e - m[dst]); segment sum ----------------
__global__ void edge_exp4(float* __restrict__ eb, const float* __restrict__ m,
                          const int* __restrict__ dst, float* __restrict__ den) {
    int i = blockIdx.x * blockDim.x + threadIdx.x;
    if (i >= EE) return;
    int d = dst[i];
    float4 e = ((const float4*)eb)[i];
    float4 mm = ((const float4*)m)[d];
    float4 ex;
    ex.x = expf(e.x - mm.x); ex.y = expf(e.y - mm.y);
    ex.z = expf(e.z - mm.z); ex.w = expf(e.w - mm.w);
    ((float4*)eb)[i] = ex;
    red_add_v4(den + d * 4, ex.x, ex.y, ex.z, ex.w);
}

__global__ void edge_exp1(float* __restrict__ eb, const float* __restrict__ m,
                          const int* __restrict__ dst, float* __restrict__ den) {
    int i = blockIdx.x * blockDim.x + threadIdx.x;
    if (i >= EE) return;
    int d = dst[i];
    float ex = expf(eb[i] - m[d]);
    eb[i] = ex;
    atomicAdd(&den[d], ex);
}

// ---------------- edge pass C: out[dst] += h[src] * alpha (warp / edge) ---------
__global__ void edge_agg4(const float* __restrict__ h, const float* __restrict__ eb,
                          const float* __restrict__ den, const int* __restrict__ src,
                          const int* __restrict__ dst, float* __restrict__ out) {
    int warp = (blockIdx.x * blockDim.x + threadIdx.x) >> 5;
    int lane = threadIdx.x & 31;
    if (warp >= EE) return;
    int s = src[warp], d = dst[warp];
    int head = lane >> 3;
    float al = eb[warp * 4 + head] / (den[d * 4 + head] + EPS);
    const float4* hr = (const float4*)(h + (size_t)s * 256);
    float4 v0 = hr[lane * 2], v1 = hr[lane * 2 + 1];
    float* orow = out + (size_t)d * 256 + lane * 8;
    red_add_v4(orow,     v0.x * al, v0.y * al, v0.z * al, v0.w * al);
    red_add_v4(orow + 4, v1.x * al, v1.y * al, v1.z * al, v1.w * al);
}

__global__ void edge_agg1(const float* __restrict__ h, const float* __restrict__ eb,
                          const float* __restrict__ den, const int* __restrict__ src,
                          const int* __restrict__ dst, float* __restrict__ out) {
    int warp = (blockIdx.x * blockDim.x + threadIdx.x) >> 5;
    int lane = threadIdx.x & 31;
    if (warp >= EE) return;
    int s = src[warp], d = dst[warp];
    float al = eb[warp] / (den[d] + EPS);
    float2 v = ((const float2*)(h + (size_t)s * 64))[lane];
    red_add_v2(out + (size_t)d * 64 + lane * 2, v.x * al, v.y * al);
}

// ---------------- bias + relu (in place) ----------------------------------------
__global__ void bias_relu(float* __restrict__ out, const float* __restrict__ b,
                          int hc_mask, int total) {
    int i = blockIdx.x * blockDim.x + threadIdx.x;
    if (i >= total) return;
    out[i] = fmaxf(out[i] + b[i & hc_mask], 0.0f);
}

// ---------------- pooling + classifier ------------------------------------------
__global__ void zero_pool(float* __restrict__ p) {
    int i = blockIdx.x * blockDim.x + threadIdx.x;
    if (i < NG * 64 + NG) p[i] = 0.0f;
}

__global__ void pool_accum(const float* __restrict__ h, const int* __restrict__ batch,
                           float* __restrict__ pool) {
    int warp = (blockIdx.x * blockDim.x + threadIdx.x) >> 5;
    int lane = threadIdx.x & 31;
    if (warp >= N_NODES) return;
    int g = batch[warp];
    float2 v = ((const float2*)(h + (size_t)warp * 64))[lane];
    red_add_v2(pool + g * 64 + lane * 2, v.x, v.y);
    if (lane == 0) atomicAdd(&pool[NG * 64 + g], 1.0f);
}

__global__ void classifier(const float* __restrict__ pool, const float* __restrict__ Wl,
                           const float* __restrict__ bl, float* __restrict__ out) {
    int t = threadIdx.x;
    if (t >= NG * NCLS) return;
    int g = t / NCLS, j = t % NCLS;
    float cnt = fmaxf(pool[NG * 64 + g], 1.0f);
    float s = 0.0f;
#pragma unroll
    for (int c = 0; c < 64; c++) s += pool[g * 64 + c] * Wl[c * NCLS + j];
    out[t] = s / cnt + bl[j];
}

// ---------------- launch --------------------------------------------------------
extern "C" void kernel_launch(void* const* d_in, const int* in_sizes, int n_in,
                              void* d_out, int out_size) {
    const float* x        = (const float*)d_in[0];
    const void*  ei       = d_in[1];
    const void*  bat      = d_in[2];
    const float* W1 = (const float*)d_in[3];
    const float* s1 = (const float*)d_in[4];
    const float* t1 = (const float*)d_in[5];
    const float* b1 = (const float*)d_in[6];
    const float* W2 = (const float*)d_in[7];
    const float* s2 = (const float*)d_in[8];
    const float* t2 = (const float*)d_in[9];
    const float* b2 = (const float*)d_in[10];
    const float* W3 = (const float*)d_in[11];
    const float* s3 = (const float*)d_in[12];
    const float* t3 = (const float*)d_in[13];
    const float* b3 = (const float*)d_in[14];
    const float* Wl = (const float*)d_in[15];
    const float* bl = (const float*)d_in[16];
    float* out = (float*)d_out;

    float *A, *B, *AS, *AD, *M, *DEN, *EB, *POOL;
    int *SRC, *DST, *BATCH;
    cudaGetSymbolAddress((void**)&A, g_bufA);
    cudaGetSymbolAddress((void**)&B, g_bufB);
    cudaGetSymbolAddress((void**)&AS, g_as);
    cudaGetSymbolAddress((void**)&AD, g_ad);
    cudaGetSymbolAddress((void**)&M, g_m);
    cudaGetSymbolAddress((void**)&DEN, g_den);
    cudaGetSymbolAddress((void**)&EB, g_e);
    cudaGetSymbolAddress((void**)&POOL, g_pool);
    cudaGetSymbolAddress((void**)&SRC, g_src);
    cudaGetSymbolAddress((void**)&DST, g_dst);
    cudaGetSymbolAddress((void**)&BATCH, g_batch);

    const int TB = 256;
    int eThr = (EE + TB - 1) / TB;                // thread per edge
    int eWarp = (EE * 32 + TB - 1) / TB;          // warp per edge
    int nWarp = (N_NODES * 32 + TB - 1) / TB;     // warp per node
    int mTiles = (N_NODES + 63) / 64;

    detect_dtypes<<<1, 32>>>(ei, bat);
    build_edges<<<eThr, TB>>>(ei, SRC, DST);
    conv_batch<<<(N_NODES + TB - 1) / TB, TB>>>(bat, BATCH);

    // ---- layer 1: 128 -> 4x64 concat ----
    sgemm<<<dim3(4, mTiles), TB>>>(x, W1, A, N_NODES, 256, 128);
    node_prep4<<<nWarp, TB>>>(A, s1, t1, AS, AD, M, DEN, B);
    edge_max4<<<eThr, TB>>>(AS, AD, SRC, DST, EB, M);
    edge_exp4<<<eThr, TB>>>(EB, M, DST, DEN);
    edge_agg4<<<eWarp, TB>>>(A, EB, DEN, SRC, DST, B);
    bias_relu<<<(N_NODES * 256 + TB - 1) / TB, TB>>>(B, b1, 255, N_NODES * 256);

    // ---- layer 2: 256 -> 4x64 concat ----
    sgemm<<<dim3(4, mTiles), TB>>>(B, W2, A, N_NODES, 256, 256);
    node_prep4<<<nWarp, TB>>>(A, s2, t2, AS, AD, M, DEN, B);
    edge_max4<<<eThr, TB>>>(AS, AD, SRC, DST, EB, M);
    edge_exp4<<<eThr, TB>>>(EB, M, DST, DEN);
    edge_agg4<<<eWarp, TB>>>(A, EB, DEN, SRC, DST, B);
    bias_relu<<<(N_NODES * 256 + TB - 1) / TB, TB>>>(B, b2, 255, N_NODES * 256);

    // ---- layer 3: 256 -> 64, heads=1, no concat ----
    sgemm<<<dim3(1, mTiles), TB>>>(B, W3, A, N_NODES, 64, 256);
    node_prep1<<<nWarp, TB>>>(A, s3, t3, AS, AD, M, DEN, B);
    edge_max1<<<eThr, TB>>>(AS, AD, SRC, DST, EB, M);
    edge_exp1<<<eThr, TB>>>(EB, M, DST, DEN);
    edge_agg1<<<eWarp, TB>>>(A, EB, DEN, SRC, DST, B);
    bias_relu<<<(N_NODES * 64 + TB - 1) / TB, TB>>>(B, b3, 63, N_NODES * 64);

    // ---- pool + classify ----
    zero_pool<<<(NG * 64 + NG + TB - 1) / TB, TB>>>(POOL);
    pool_accum<<<nWarp, TB>>>(B, BATCH, POOL);
    classifier<<<1, 640>>>(POOL, Wl, bl, out);
}

// round 4
// speedup vs baseline: 1.8227x; 1.8227x over previous
#include <cuda_runtime.h>

#define N_NODES 50000
#define N_EDGES 800000
#define EE (N_EDGES + N_NODES)   // edges + self loops = 850000
#define NG 64
#define NCLS 10
#define NEG_SLOPE 0.2f
#define EPS 1e-16f
#define NB_SCAN ((N_NODES + 255) / 256)   // 196 scan blocks

// ---------------- scratch (static device globals; no runtime alloc) -------------
__device__ __align__(16) float g_bufA[N_NODES * 256];   // gemm output (h) per layer
__device__ __align__(16) float g_bufB[N_NODES * 256];   // gat output per layer
__device__ __align__(16) float g_as[N_NODES * 4];
__device__ __align__(16) float g_ad[N_NODES * 4];
__device__ __align__(16) float g_e[EE * 4];
__device__ __align__(16) int   g_src[EE];
__device__ __align__(16) int   g_dst[EE];
__device__ __align__(16) int   g_batch[N_NODES];
__device__ __align__(16) int   g_deg[N_NODES];
__device__ __align__(16) int   g_incl[N_NODES];
__device__ __align__(16) int   g_bsum[256];
__device__ __align__(16) int   g_off[N_NODES + 1];
__device__ __align__(16) int   g_cursor[N_NODES];
__device__ __align__(16) int   g_csr_src[EE];
__device__ __align__(16) float g_pool[NG * 64 + NG];    // sums [64,64] then counts [64]
__device__ int g_flags[2];

// ---------------- helpers -------------------------------------------------------
__device__ __forceinline__ void red_add_v2(float* addr, float a, float b) {
    asm volatile("red.global.add.v2.f32 [%0], {%1,%2};"
                 :: "l"(addr), "f"(a), "f"(b) : "memory");
}
__device__ __forceinline__ float lrelu(float v) { return v >= 0.0f ? v : NEG_SLOPE * v; }

// ---------------- dtype detection (JAX may give int32 despite int64 request) ----
__global__ void detect_dtypes(const void* ei, const void* bat) {
    if (threadIdx.x != 0 || blockIdx.x != 0) return;
    const long long* e64 = (const long long*)ei;
    int ok = 1;
    for (int i = 0; i < 8; i++) {
        long long v = e64[i];
        if (v < 0 || v >= N_NODES) ok = 0;
    }
    g_flags[0] = ok;
    const long long* b64 = (const long long*)bat;
    int okb = 1;
    for (int i = 0; i < 8; i++) {
        long long v = b64[N_NODES / 2 - 1 - i];
        if (v < 0 || v >= NG) okb = 0;
    }
    g_flags[1] = okb;
}

// ---------------- edge list build (append self loops) ---------------------------
__global__ void build_edges(const void* ei, int* __restrict__ src, int* __restrict__ dst) {
    int i = blockIdx.x * blockDim.x + threadIdx.x;
    if (i >= EE) return;
    if (i < N_EDGES) {
        if (g_flags[0]) {
            const long long* e = (const long long*)ei;
            src[i] = (int)e[i];
            dst[i] = (int)e[N_EDGES + i];
        } else {
            const int* e = (const int*)ei;
            src[i] = e[i];
            dst[i] = e[N_EDGES + i];
        }
    } else {
        int n = i - N_EDGES;
        src[i] = n;
        dst[i] = n;
    }
}

__global__ void conv_batch(const void* bat, int* __restrict__ out) {
    int i = blockIdx.x * blockDim.x + threadIdx.x;
    if (i >= N_NODES) return;
    if (g_flags[1]) out[i] = (int)((const long long*)bat)[i];
    else            out[i] = ((const int*)bat)[i];
}

// ---------------- CSR build: histogram + scan + scatter -------------------------
__global__ void zero_deg(int* __restrict__ deg) {
    int i = blockIdx.x * blockDim.x + threadIdx.x;
    if (i < N_NODES) deg[i] = 0;
}

__global__ void hist_dst(const int* __restrict__ dst, int* __restrict__ deg) {
    int i = blockIdx.x * blockDim.x + threadIdx.x;
    if (i < EE) atomicAdd(&deg[dst[i]], 1);
}

// per-block inclusive scan (256 elems), write inclusive partials + block sums
__global__ void scan1(const int* __restrict__ deg, int* __restrict__ incl,
                      int* __restrict__ bsum) {
    __shared__ int s[256];
    int t = threadIdx.x;
    int i = blockIdx.x * 256 + t;
    int v = (i < N_NODES) ? deg[i] : 0;
    s[t] = v;
    __syncthreads();
#pragma unroll
    for (int o = 1; o < 256; o <<= 1) {
        int x = (t >= o) ? s[t - o] : 0;
        __syncthreads();
        s[t] += x;
        __syncthreads();
    }
    if (i < N_NODES) incl[i] = s[t];
    if (t == 255) bsum[blockIdx.x] = s[255];
}

// exclusive scan of block sums (NB_SCAN <= 256) in place
__global__ void scan2(int* __restrict__ bsum) {
    __shared__ int s[256];
    int t = threadIdx.x;
    int v = (t < NB_SCAN) ? bsum[t] : 0;
    s[t] = v;
    __syncthreads();
#pragma unroll
    for (int o = 1; o < 256; o <<= 1) {
        int x = (t >= o) ? s[t - o] : 0;
        __syncthreads();
        s[t] += x;
        __syncthreads();
    }
    bsum[t] = s[t] - v;   // exclusive
}

__global__ void scan3(const int* __restrict__ deg, const int* __restrict__ incl,
                      const int* __restrict__ bsum, int* __restrict__ off,
                      int* __restrict__ cursor) {
    int i = blockIdx.x * blockDim.x + threadIdx.x;
    if (i >= N_NODES) return;
    int o = incl[i] - deg[i] + bsum[i >> 8];   // exclusive offset
    off[i] = o;
    cursor[i] = o;
    if (i == 0) off[N_NODES] = EE;
}

__global__ void scatter_csr(const int* __restrict__ src, const int* __restrict__ dst,
                            int* __restrict__ cursor, int* __restrict__ csr_src) {
    int i = blockIdx.x * blockDim.x + threadIdx.x;
    if (i >= EE) return;
    int pos = atomicAdd(&cursor[dst[i]], 1);
    csr_src[pos] = src[i];
}

// ---------------- SGEMM 128x128 tile, BK=16, 256 thr, 8x8/thr -------------------
// requires N % 128 == 0, K % 16 == 0; M arbitrary
__global__ void sgemm128(const float* __restrict__ A, const float* __restrict__ B,
                         float* __restrict__ C, int M, int N, int K) {
    __shared__ float As[16][128];   // transposed: As[k][m]
    __shared__ float Bs[16][128];
    int tid = threadIdx.x;
    int m0 = blockIdx.y * 128, n0 = blockIdx.x * 128;
    int ty = tid >> 4, tx = tid & 15;
    float acc[8][8] = {};

    for (int k0 = 0; k0 < K; k0 += 16) {
#pragma unroll
        for (int i = 0; i < 2; i++) {
            int f = tid * 2 + i;
            int row = f >> 2, c4 = (f & 3) << 2;
            float4 av = make_float4(0.f, 0.f, 0.f, 0.f);
            if (m0 + row < M)
                av = *(const float4*)(A + (size_t)(m0 + row) * K + k0 + c4);
            As[c4 + 0][row] = av.x; As[c4 + 1][row] = av.y;
            As[c4 + 2][row] = av.z; As[c4 + 3][row] = av.w;
        }
#pragma unroll
        for (int i = 0; i < 2; i++) {
            int f = tid * 2 + i;
            int row = f >> 5, c4 = (f & 31) << 2;
            *(float4*)&Bs[row][c4] = *(const float4*)(B + (size_t)(k0 + row) * N + n0 + c4);
        }
        __syncthreads();
#pragma unroll
        for (int k = 0; k < 16; k++) {
            float a[8], b[8];
            *(float4*)a       = *(const float4*)&As[k][ty * 8];
            *(float4*)(a + 4) = *(const float4*)&As[k][ty * 8 + 4];
            *(float4*)b       = *(const float4*)&Bs[k][tx * 8];
            *(float4*)(b + 4) = *(const float4*)&Bs[k][tx * 8 + 4];
#pragma unroll
            for (int ii = 0; ii < 8; ii++)
#pragma unroll
                for (int jj = 0; jj < 8; jj++) acc[ii][jj] += a[ii] * b[jj];
        }
        __syncthreads();
    }
#pragma unroll
    for (int ii = 0; ii < 8; ii++) {
        int row = m0 + ty * 8 + ii;
        if (row < M) {
            *(float4*)(C + (size_t)row * N + n0 + tx * 8)     = *(float4*)&acc[ii][0];
            *(float4*)(C + (size_t)row * N + n0 + tx * 8 + 4) = *(float4*)&acc[ii][4];
        }
    }
}

// ---------------- SGEMM 64x64 tile (for N=64 layer 3) ---------------------------
__global__ void sgemm64(const float* __restrict__ A, const float* __restrict__ B,
                        float* __restrict__ C, int M, int N, int K) {
    __shared__ float As[16][64];
    __shared__ float Bs[16][64];
    int tid = threadIdx.x;
    int tx = tid & 15, ty = tid >> 4;
    int m0 = blockIdx.y * 64, n0 = blockIdx.x * 64;
    float acc[4][4] = {};
    int ar = tid >> 2, ac = (tid & 3) << 2;
    int br = tid >> 4, bc = (tid & 15) << 2;

    for (int k0 = 0; k0 < K; k0 += 16) {
        float4 av = make_float4(0.f, 0.f, 0.f, 0.f);
        if (m0 + ar < M)
            av = *(const float4*)(A + (size_t)(m0 + ar) * K + k0 + ac);
        As[ac + 0][ar] = av.x; As[ac + 1][ar] = av.y;
        As[ac + 2][ar] = av.z; As[ac + 3][ar] = av.w;
        float4 bv = *(const float4*)(B + (size_t)(k0 + br) * N + n0 + bc);
        *(float4*)&Bs[br][bc] = bv;
        __syncthreads();
#pragma unroll
        for (int k = 0; k < 16; k++) {
            float a[4], b[4];
#pragma unroll
            for (int i = 0; i < 4; i++) a[i] = As[k][ty * 4 + i];
#pragma unroll
            for (int j = 0; j < 4; j++) b[j] = Bs[k][tx * 4 + j];
#pragma unroll
            for (int i = 0; i < 4; i++)
#pragma unroll
                for (int j = 0; j < 4; j++) acc[i][j] += a[i] * b[j];
        }
        __syncthreads();
    }
#pragma unroll
    for (int i = 0; i < 4; i++) {
        int row = m0 + ty * 4 + i;
        if (row < M) {
#pragma unroll
            for (int j = 0; j < 4; j++)
                C[(size_t)row * N + n0 + tx * 4 + j] = acc[i][j];
        }
    }
}

// ---------------- attention dot products (per node) -----------------------------
// H=4, C=64: one warp per node
__global__ void dots4(const float* __restrict__ h, const float* __restrict__ a_src,
                      const float* __restrict__ a_dst, float* __restrict__ as,
                      float* __restrict__ ad) {
    int warp = (blockIdx.x * blockDim.x + threadIdx.x) >> 5;
    int lane = threadIdx.x & 31;
    if (warp >= N_NODES) return;
    const float4* hr = (const float4*)(h + (size_t)warp * 256);
    const float4* sr = (const float4*)a_src;
    const float4* dr = (const float4*)a_dst;
    float4 h0 = hr[lane * 2], h1 = hr[lane * 2 + 1];
    float4 s0 = sr[lane * 2], s1 = sr[lane * 2 + 1];
    float4 d0 = dr[lane * 2], d1 = dr[lane * 2 + 1];
    float ps = h0.x * s0.x + h0.y * s0.y + h0.z * s0.z + h0.w * s0.w +
               h1.x * s1.x + h1.y * s1.y + h1.z * s1.z + h1.w * s1.w;
    float pd = h0.x * d0.x + h0.y * d0.y + h0.z * d0.z + h0.w * d0.w +
               h1.x * d1.x + h1.y * d1.y + h1.z * d1.z + h1.w * d1.w;
#pragma unroll
    for (int o = 4; o >= 1; o >>= 1) {
        ps += __shfl_down_sync(0xffffffffu, ps, o, 8);
        pd += __shfl_down_sync(0xffffffffu, pd, o, 8);
    }
    if ((lane & 7) == 0) {
        int hd = lane >> 3;
        as[warp * 4 + hd] = ps;
        ad[warp * 4 + hd] = pd;
    }
}

__global__ void dots1(const float* __restrict__ h, const float* __restrict__ a_src,
                      const float* __restrict__ a_dst, float* __restrict__ as,
                      float* __restrict__ ad) {
    int warp = (blockIdx.x * blockDim.x + threadIdx.x) >> 5;
    int lane = threadIdx.x & 31;
    if (warp >= N_NODES) return;
    float2 hv = ((const float2*)(h + (size_t)warp * 64))[lane];
    float2 sv = ((const float2*)a_src)[lane];
    float2 dv = ((const float2*)a_dst)[lane];
    float ps = hv.x * sv.x + hv.y * sv.y;
    float pd = hv.x * dv.x + hv.y * dv.y;
#pragma unroll
    for (int o = 16; o >= 1; o >>= 1) {
        ps += __shfl_down_sync(0xffffffffu, ps, o);
        pd += __shfl_down_sync(0xffffffffu, pd, o);
    }
    if (lane == 0) {
        as[warp] = ps;
        ad[warp] = pd;
    }
}

// ---------------- fused GAT layer (softmax + aggregate + bias + relu) -----------
// H=4: one warp per dst node, iterates its incoming edges via CSR.
__global__ void gat_node4(const float* __restrict__ h, const float* __restrict__ as,
                          const float* __restrict__ ad, const int* __restrict__ off,
                          const int* __restrict__ csr_src, float* __restrict__ eb,
                          const float* __restrict__ bias, float* __restrict__ out) {
    int node = (blockIdx.x * blockDim.x + threadIdx.x) >> 5;
    int lane = threadIdx.x & 31;
    if (node >= N_NODES) return;
    int start = off[node], end = off[node + 1];
    float4 adv = ((const float4*)ad)[node];

    // phase A: e = leaky(as[src] + ad[node]); warp max per head
    float4 mx = make_float4(-INFINITY, -INFINITY, -INFINITY, -INFINITY);
    for (int k = start + lane; k < end; k += 32) {
        int s = csr_src[k];
        float4 a = ((const float4*)as)[s];
        float4 e;
        e.x = lrelu(a.x + adv.x); e.y = lrelu(a.y + adv.y);
        e.z = lrelu(a.z + adv.z); e.w = lrelu(a.w + adv.w);
        ((float4*)eb)[k] = e;
        mx.x = fmaxf(mx.x, e.x); mx.y = fmaxf(mx.y, e.y);
        mx.z = fmaxf(mx.z, e.z); mx.w = fmaxf(mx.w, e.w);
    }
#pragma unroll
    for (int o = 16; o >= 1; o >>= 1) {
        mx.x = fmaxf(mx.x, __shfl_xor_sync(0xffffffffu, mx.x, o));
        mx.y = fmaxf(mx.y, __shfl_xor_sync(0xffffffffu, mx.y, o));
        mx.z = fmaxf(mx.z, __shfl_xor_sync(0xffffffffu, mx.z, o));
        mx.w = fmaxf(mx.w, __shfl_xor_sync(0xffffffffu, mx.w, o));
    }
    __syncwarp();

    // phase B: accumulate numerator (8 floats/lane) and denominator per head
    int head = lane >> 3;
    float mh = head == 0 ? mx.x : head == 1 ? mx.y : head == 2 ? mx.z : mx.w;
    float acc[8] = {};
    float den = 0.0f;
    const float4* hb = (const float4*)h;
    for (int k = start; k < end; k++) {
        int s = csr_src[k];
        float4 e4 = ((const float4*)eb)[k];
        float eh = head == 0 ? e4.x : head == 1 ? e4.y : head == 2 ? e4.z : e4.w;
        float ex = __expf(eh - mh);
        den += ex;
        const float4* hr = hb + (size_t)s * 64 + lane * 2;
        float4 v0 = hr[0], v1 = hr[1];
        acc[0] += v0.x * ex; acc[1] += v0.y * ex; acc[2] += v0.z * ex; acc[3] += v0.w * ex;
        acc[4] += v1.x * ex; acc[5] += v1.y * ex; acc[6] += v1.z * ex; acc[7] += v1.w * ex;
    }
    float inv = 1.0f / (den + EPS);
    const float* bp = bias + lane * 8;
    float4 o0, o1;
    o0.x = fmaxf(acc[0] * inv + bp[0], 0.f); o0.y = fmaxf(acc[1] * inv + bp[1], 0.f);
    o0.z = fmaxf(acc[2] * inv + bp[2], 0.f); o0.w = fmaxf(acc[3] * inv + bp[3], 0.f);
    o1.x = fmaxf(acc[4] * inv + bp[4], 0.f); o1.y = fmaxf(acc[5] * inv + bp[5], 0.f);
    o1.z = fmaxf(acc[6] * inv + bp[6], 0.f); o1.w = fmaxf(acc[7] * inv + bp[7], 0.f);
    float4* orow = (float4*)(out + (size_t)node * 256) + lane * 2;
    orow[0] = o0;
    orow[1] = o1;
}

// H=1, C=64 final layer: fused softmax+agg+bias+relu+POOL (h3 never materialized)
__global__ void gat_node1_pool(const float* __restrict__ h, const float* __restrict__ as,
                               const float* __restrict__ ad, const int* __restrict__ off,
                               const int* __restrict__ csr_src, float* __restrict__ eb,
                               const float* __restrict__ bias, const int* __restrict__ batch,
                               float* __restrict__ pool) {
    int node = (blockIdx.x * blockDim.x + threadIdx.x) >> 5;
    int lane = threadIdx.x & 31;
    if (node >= N_NODES) return;
    int start = off[node], end = off[node + 1];
    float adv = ad[node];

    float mx = -INFINITY;
    for (int k = start + lane; k < end; k += 32) {
        float e = lrelu(as[csr_src[k]] + adv);
        eb[k] = e;
        mx = fmaxf(mx, e);
    }
#pragma unroll
    for (int o = 16; o >= 1; o >>= 1)
        mx = fmaxf(mx, __shfl_xor_sync(0xffffffffu, mx, o));
    __syncwarp();

    float acc0 = 0.f, acc1 = 0.f, den = 0.f;
    const float2* hb = (const float2*)h;
    for (int k = start; k < end; k++) {
        int s = csr_src[k];
        float ex = __expf(eb[k] - mx);
        den += ex;
        float2 v = hb[(size_t)s * 32 + lane];
        acc0 += v.x * ex;
        acc1 += v.y * ex;
    }
    float inv = 1.0f / (den + EPS);
    float o0 = fmaxf(acc0 * inv + bias[lane * 2], 0.f);
    float o1 = fmaxf(acc1 * inv + bias[lane * 2 + 1], 0.f);
    int g = batch[node];
    red_add_v2(pool + g * 64 + lane * 2, o0, o1);
    if (lane == 0) atomicAdd(&pool[NG * 64 + g], 1.0f);
}

// ---------------- pooling + classifier ------------------------------------------
__global__ void zero_pool(float* __restrict__ p) {
    int i = blockIdx.x * blockDim.x + threadIdx.x;
    if (i < NG * 64 + NG) p[i] = 0.0f;
}

__global__ void classifier(const float* __restrict__ pool, const float* __restrict__ Wl,
                           const float* __restrict__ bl, float* __restrict__ out) {
    int t = threadIdx.x;
    if (t >= NG * NCLS) return;
    int g = t / NCLS, j = t % NCLS;
    float cnt = fmaxf(pool[NG * 64 + g], 1.0f);
    float s = 0.0f;
#pragma unroll
    for (int c = 0; c < 64; c++) s += pool[g * 64 + c] * Wl[c * NCLS + j];
    out[t] = s / cnt + bl[j];
}

// ---------------- launch --------------------------------------------------------
extern "C" void kernel_launch(void* const* d_in, const int* in_sizes, int n_in,
                              void* d_out, int out_size) {
    const float* x   = (const float*)d_in[0];
    const void*  ei  = d_in[1];
    const void*  bat = d_in[2];
    const float* W1 = (const float*)d_in[3];
    const float* s1 = (const float*)d_in[4];
    const float* t1 = (const float*)d_in[5];
    const float* b1 = (const float*)d_in[6];
    const float* W2 = (const float*)d_in[7];
    const float* s2 = (const float*)d_in[8];
    const float* t2 = (const float*)d_in[9];
    const float* b2 = (const float*)d_in[10];
    const float* W3 = (const float*)d_in[11];
    const float* s3 = (const float*)d_in[12];
    const float* t3 = (const float*)d_in[13];
    const float* b3 = (const float*)d_in[14];
    const float* Wl = (const float*)d_in[15];
    const float* bl = (const float*)d_in[16];
    float* out = (float*)d_out;

    float *A, *B, *AS, *AD, *EB, *POOL;
    int *SRC, *DST, *BATCH, *DEG, *INCL, *BSUM, *OFF, *CUR, *CSR;
    cudaGetSymbolAddress((void**)&A, g_bufA);
    cudaGetSymbolAddress((void**)&B, g_bufB);
    cudaGetSymbolAddress((void**)&AS, g_as);
    cudaGetSymbolAddress((void**)&AD, g_ad);
    cudaGetSymbolAddress((void**)&EB, g_e);
    cudaGetSymbolAddress((void**)&POOL, g_pool);
    cudaGetSymbolAddress((void**)&SRC, g_src);
    cudaGetSymbolAddress((void**)&DST, g_dst);
    cudaGetSymbolAddress((void**)&BATCH, g_batch);
    cudaGetSymbolAddress((void**)&DEG, g_deg);
    cudaGetSymbolAddress((void**)&INCL, g_incl);
    cudaGetSymbolAddress((void**)&BSUM, g_bsum);
    cudaGetSymbolAddress((void**)&OFF, g_off);
    cudaGetSymbolAddress((void**)&CUR, g_cursor);
    cudaGetSymbolAddress((void**)&CSR, g_csr_src);

    const int TB = 256;
    int eThr = (EE + TB - 1) / TB;
    int nThr = (N_NODES + TB - 1) / TB;
    int nWarp = (N_NODES * 32 + TB - 1) / TB;

    detect_dtypes<<<1, 32>>>(ei, bat);
    build_edges<<<eThr, TB>>>(ei, SRC, DST);
    conv_batch<<<nThr, TB>>>(bat, BATCH);

    // CSR by dst
    zero_deg<<<nThr, TB>>>(DEG);
    hist_dst<<<eThr, TB>>>(DST, DEG);
    scan1<<<NB_SCAN, 256>>>(DEG, INCL, BSUM);
    scan2<<<1, 256>>>(BSUM);
    scan3<<<nThr, TB>>>(DEG, INCL, BSUM, OFF, CUR);
    scatter_csr<<<eThr, TB>>>(SRC, DST, CUR, CSR);

    int mT128 = (N_NODES + 127) / 128;
    int mT64  = (N_NODES + 63) / 64;

    // ---- layer 1: 128 -> 4x64 concat ----
    sgemm128<<<dim3(2, mT128), TB>>>(x, W1, A, N_NODES, 256, 128);
    dots4<<<nWarp, TB>>>(A, s1, t1, AS, AD);
    gat_node4<<<nWarp, TB>>>(A, AS, AD, OFF, CSR, EB, b1, B);

    // ---- layer 2: 256 -> 4x64 concat ----
    sgemm128<<<dim3(2, mT128), TB>>>(B, W2, A, N_NODES, 256, 256);
    dots4<<<nWarp, TB>>>(A, s2, t2, AS, AD);
    gat_node4<<<nWarp, TB>>>(A, AS, AD, OFF, CSR, EB, b2, B);

    // ---- layer 3: 256 -> 64, heads=1, no concat; fused with pooling ----
    sgemm64<<<dim3(1, mT64), TB>>>(B, W3, A, N_NODES, 64, 256);
    dots1<<<nWarp, TB>>>(A, s3, t3, AS, AD);
    zero_pool<<<(NG * 64 + NG + TB - 1) / TB, TB>>>(POOL);
    gat_node1_pool<<<nWarp, TB>>>(A, AS, AD, OFF, CSR, EB, b3, BATCH, POOL);

    classifier<<<1, 640>>>(POOL, Wl, bl, out);
}

// round 6
// speedup vs baseline: 2.6643x; 1.4617x over previous
#include <cuda_runtime.h>
#include <cstdint>

#define N_NODES 50000
#define N_EDGES 800000
#define EE (N_EDGES + N_NODES)   // edges + self loops = 850000
#define NG 64
#define NCLS 10
#define NEG_SLOPE 0.2f
#define EPS 1e-16f
#define NB_SCAN ((N_NODES + 255) / 256)

// ---------------- scratch (static device globals; no runtime alloc) -------------
__device__ __align__(16) float g_bufA[N_NODES * 256];
__device__ __align__(16) float g_bufB[N_NODES * 256];
__device__ __align__(16) float g_as[N_NODES * 4];
__device__ __align__(16) float g_ad[N_NODES * 4];
__device__ __align__(16) int   g_src[EE];
__device__ __align__(16) int   g_dst[EE];
__device__ __align__(16) int   g_batch[N_NODES];
__device__ __align__(16) int   g_deg[N_NODES];
__device__ __align__(16) int   g_incl[N_NODES];
__device__ __align__(16) int   g_bsum[256];
__device__ __align__(16) int   g_off[N_NODES + 1];
__device__ __align__(16) int   g_cursor[N_NODES];
__device__ __align__(16) int   g_csr_src[EE];
__device__ __align__(16) float g_pool[NG * 64 + NG];
__device__ int g_flags[2];

// ---------------- helpers -------------------------------------------------------
__device__ __forceinline__ void red_add_v2(float* addr, float a, float b) {
    asm volatile("red.global.add.v2.f32 [%0], {%1,%2};"
                 :: "l"(addr), "f"(a), "f"(b) : "memory");
}
__device__ __forceinline__ float lrelu(float v) { return v >= 0.0f ? v : NEG_SLOPE * v; }

__device__ __forceinline__ float f2tf32(float x) {
    uint32_t r;
    asm("cvt.rna.tf32.f32 %0, %1;" : "=r"(r) : "f"(x));
    return __uint_as_float(r);
}

__device__ __forceinline__ void mma_tf32(float* d, uint32_t a0, uint32_t a1,
                                         uint32_t a2, uint32_t a3,
                                         uint32_t b0, uint32_t b1) {
    asm("mma.sync.aligned.m16n8k8.row.col.f32.tf32.tf32.f32 "
        "{%0,%1,%2,%3},{%4,%5,%6,%7},{%8,%9},{%0,%1,%2,%3};"
        : "+f"(d[0]), "+f"(d[1]), "+f"(d[2]), "+f"(d[3])
        : "r"(a0), "r"(a1), "r"(a2), "r"(a3), "r"(b0), "r"(b1));
}

// ---------------- dtype detection (JAX may give int32 despite int64 request) ----
__global__ void detect_dtypes(const void* ei, const void* bat) {
    if (threadIdx.x != 0 || blockIdx.x != 0) return;
    const long long* e64 = (const long long*)ei;
    int ok = 1;
    for (int i = 0; i < 8; i++) {
        long long v = e64[i];
        if (v < 0 || v >= N_NODES) ok = 0;
    }
    g_flags[0] = ok;
    const long long* b64 = (const long long*)bat;
    int okb = 1;
    for (int i = 0; i < 8; i++) {
        long long v = b64[N_NODES / 2 - 1 - i];
        if (v < 0 || v >= NG) okb = 0;
    }
    g_flags[1] = okb;
}

// ---------------- edge list build (append self loops) ---------------------------
__global__ void build_edges(const void* ei, int* __restrict__ src, int* __restrict__ dst) {
    int i = blockIdx.x * blockDim.x + threadIdx.x;
    if (i >= EE) return;
    if (i < N_EDGES) {
        if (g_flags[0]) {
            const long long* e = (const long long*)ei;
            src[i] = (int)e[i];
            dst[i] = (int)e[N_EDGES + i];
        } else {
            const int* e = (const int*)ei;
            src[i] = e[i];
            dst[i] = e[N_EDGES + i];
        }
    } else {
        int n = i - N_EDGES;
        src[i] = n;
        dst[i] = n;
    }
}

__global__ void conv_batch(const void* bat, int* __restrict__ out) {
    int i = blockIdx.x * blockDim.x + threadIdx.x;
    if (i >= N_NODES) return;
    if (g_flags[1]) out[i] = (int)((const long long*)bat)[i];
    else            out[i] = ((const int*)bat)[i];
}

// ---------------- CSR build: histogram + scan + scatter -------------------------
__global__ void zero_deg(int* __restrict__ deg) {
    int i = blockIdx.x * blockDim.x + threadIdx.x;
    if (i < N_NODES) deg[i] = 0;
}

__global__ void hist_dst(const int* __restrict__ dst, int* __restrict__ deg) {
    int i = blockIdx.x * blockDim.x + threadIdx.x;
    if (i < EE) atomicAdd(&deg[dst[i]], 1);
}

__global__ void scan1(const int* __restrict__ deg, int* __restrict__ incl,
                      int* __restrict__ bsum) {
    __shared__ int s[256];
    int t = threadIdx.x;
    int i = blockIdx.x * 256 + t;
    int v = (i < N_NODES) ? deg[i] : 0;
    s[t] = v;
    __syncthreads();
#pragma unroll
    for (int o = 1; o < 256; o <<= 1) {
        int x = (t >= o) ? s[t - o] : 0;
        __syncthreads();
        s[t] += x;
        __syncthreads();
    }
    if (i < N_NODES) incl[i] = s[t];
    if (t == 255) bsum[blockIdx.x] = s[255];
}

__global__ void scan2(int* __restrict__ bsum) {
    __shared__ int s[256];
    int t = threadIdx.x;
    int v = (t < NB_SCAN) ? bsum[t] : 0;
    s[t] = v;
    __syncthreads();
#pragma unroll
    for (int o = 1; o < 256; o <<= 1) {
        int x = (t >= o) ? s[t - o] : 0;
        __syncthreads();
        s[t] += x;
        __syncthreads();
    }
    bsum[t] = s[t] - v;
}

__global__ void scan3(const int* __restrict__ deg, const int* __restrict__ incl,
                      const int* __restrict__ bsum, int* __restrict__ off,
                      int* __restrict__ cursor) {
    int i = blockIdx.x * blockDim.x + threadIdx.x;
    if (i >= N_NODES) return;
    int o = incl[i] - deg[i] + bsum[i >> 8];
    off[i] = o;
    cursor[i] = o;
    if (i == 0) off[N_NODES] = EE;
}

__global__ void scatter_csr(const int* __restrict__ src, const int* __restrict__ dst,
                            int* __restrict__ cursor, int* __restrict__ csr_src) {
    int i = blockIdx.x * blockDim.x + threadIdx.x;
    if (i >= EE) return;
    int pos = atomicAdd(&cursor[dst[i]], 1);
    csr_src[pos] = src[i];
}

// ---------------- TF32 tensor-core GEMM -----------------------------------------
// C[M,N] = A[M,K] @ B[K,N]; BM=128, BN template (128 or 64), BK=16.
// 256 threads = 8 warps in 2(M) x 4(N); warp tile 64 x (BN/4).
// SMEM stride 136 -> fragment LDS bank = 8*(lane&3)+(lane>>2): conflict-free.
template <int BN>
__global__ void mma_gemm(const float* __restrict__ A, const float* __restrict__ Bm,
                         float* __restrict__ C, int M, int N, int K) {
    constexpr int WN = BN / 4;      // warp n-width
    constexpr int NT = WN / 8;      // n-tiles (m16n8) per warp
    __shared__ float As[16][136];
    __shared__ float Bs[16][BN + 8];
    int tid = threadIdx.x;
    int lane = tid & 31, warp = tid >> 5;
    int wm = (warp & 1) * 64, wn = (warp >> 1) * WN;
    int m0 = blockIdx.y * 128, n0 = blockIdx.x * BN;
    int l3 = lane & 3, l2 = lane >> 2;

    float acc[4][NT][4] = {};

    for (int k0 = 0; k0 < K; k0 += 16) {
        // A tile 128x16 -> As[k][m] transposed, tf32-converted
#pragma unroll
        for (int i = 0; i < 2; i++) {
            int f = tid * 2 + i;
            int row = f >> 2, c4 = (f & 3) << 2;
            float4 av = make_float4(0.f, 0.f, 0.f, 0.f);
            if (m0 + row < M)
                av = *(const float4*)(A + (size_t)(m0 + row) * K + k0 + c4);
            As[c4 + 0][row] = f2tf32(av.x);
            As[c4 + 1][row] = f2tf32(av.y);
            As[c4 + 2][row] = f2tf32(av.z);
            As[c4 + 3][row] = f2tf32(av.w);
        }
        // B tile 16xBN -> Bs[k][n], tf32-converted
        if (BN == 128) {
#pragma unroll
            for (int i = 0; i < 2; i++) {
                int f = tid * 2 + i;
                int row = f >> 5, c4 = (f & 31) << 2;
                float4 bv = *(const float4*)(Bm + (size_t)(k0 + row) * N + n0 + c4);
                Bs[row][c4 + 0] = f2tf32(bv.x);
                Bs[row][c4 + 1] = f2tf32(bv.y);
                Bs[row][c4 + 2] = f2tf32(bv.z);
                Bs[row][c4 + 3] = f2tf32(bv.w);
            }
        } else {
            int row = tid >> 4, c4 = (tid & 15) << 2;
            float4 bv = *(const float4*)(Bm + (size_t)(k0 + row) * N + n0 + c4);
            Bs[row][c4 + 0] = f2tf32(bv.x);
            Bs[row][c4 + 1] = f2tf32(bv.y);
            Bs[row][c4 + 2] = f2tf32(bv.z);
            Bs[row][c4 + 3] = f2tf32(bv.w);
        }
        __syncthreads();

#pragma unroll
        for (int kk = 0; kk < 16; kk += 8) {
            uint32_t bf[NT][2];
#pragma unroll
            for (int j = 0; j < NT; j++) {
                bf[j][0] = __float_as_uint(Bs[kk + l3][wn + j * 8 + l2]);
                bf[j][1] = __float_as_uint(Bs[kk + l3 + 4][wn + j * 8 + l2]);
            }
#pragma unroll
            for (int i = 0; i < 4; i++) {
                uint32_t a0 = __float_as_uint(As[kk + l3][wm + i * 16 + l2]);
                uint32_t a1 = __float_as_uint(As[kk + l3][wm + i * 16 + l2 + 8]);
                uint32_t a2 = __float_as_uint(As[kk + l3 + 4][wm + i * 16 + l2]);
                uint32_t a3 = __float_as_uint(As[kk + l3 + 4][wm + i * 16 + l2 + 8]);
#pragma unroll
                for (int j = 0; j < NT; j++)
                    mma_tf32(acc[i][j], a0, a1, a2, a3, bf[j][0], bf[j][1]);
            }
        }
        __syncthreads();
    }

#pragma unroll
    for (int i = 0; i < 4; i++) {
#pragma unroll
        for (int j = 0; j < NT; j++) {
            int r0 = m0 + wm + i * 16 + l2;
            int c = n0 + wn + j * 8 + 2 * l3;
            if (r0 < M)
                *(float2*)(C + (size_t)r0 * N + c) = make_float2(acc[i][j][0], acc[i][j][1]);
            if (r0 + 8 < M)
                *(float2*)(C + (size_t)(r0 + 8) * N + c) = make_float2(acc[i][j][2], acc[i][j][3]);
        }
    }
}

// ---------------- attention dot products (per node) -----------------------------
__global__ void dots4(const float* __restrict__ h, const float* __restrict__ a_src,
                      const float* __restrict__ a_dst, float* __restrict__ as,
                      float* __restrict__ ad) {
    int warp = (blockIdx.x * blockDim.x + threadIdx.x) >> 5;
    int lane = threadIdx.x & 31;
    if (warp >= N_NODES) return;
    const float4* hr = (const float4*)(h + (size_t)warp * 256);
    const float4* sr = (const float4*)a_src;
    const float4* dr = (const float4*)a_dst;
    float4 h0 = hr[lane * 2], h1 = hr[lane * 2 + 1];
    float4 s0 = sr[lane * 2], s1 = sr[lane * 2 + 1];
    float4 d0 = dr[lane * 2], d1 = dr[lane * 2 + 1];
    float ps = h0.x * s0.x + h0.y * s0.y + h0.z * s0.z + h0.w * s0.w +
               h1.x * s1.x + h1.y * s1.y + h1.z * s1.z + h1.w * s1.w;
    float pd = h0.x * d0.x + h0.y * d0.y + h0.z * d0.z + h0.w * d0.w +
               h1.x * d1.x + h1.y * d1.y + h1.z * d1.z + h1.w * d1.w;
#pragma unroll
    for (int o = 4; o >= 1; o >>= 1) {
        ps += __shfl_down_sync(0xffffffffu, ps, o, 8);
        pd += __shfl_down_sync(0xffffffffu, pd, o, 8);
    }
    if ((lane & 7) == 0) {
        int hd = lane >> 3;
        as[warp * 4 + hd] = ps;
        ad[warp * 4 + hd] = pd;
    }
}

__global__ void dots1(const float* __restrict__ h, const float* __restrict__ a_src,
                      const float* __restrict__ a_dst, float* __restrict__ as,
                      float* __restrict__ ad) {
    int warp = (blockIdx.x * blockDim.x + threadIdx.x) >> 5;
    int lane = threadIdx.x & 31;
    if (warp >= N_NODES) return;
    float2 hv = ((const float2*)(h + (size_t)warp * 64))[lane];
    float2 sv = ((const float2*)a_src)[lane];
    float2 dv = ((const float2*)a_dst)[lane];
    float ps = hv.x * sv.x + hv.y * sv.y;
    float pd = hv.x * dv.x + hv.y * dv.y;
#pragma unroll
    for (int o = 16; o >= 1; o >>= 1) {
        ps += __shfl_down_sync(0xffffffffu, ps, o);
        pd += __shfl_down_sync(0xffffffffu, pd, o);
    }
    if (lane == 0) {
        as[warp] = ps;
        ad[warp] = pd;
    }
}

// ---------------- fused GAT layer (softmax + aggregate + bias + relu) -----------
// H=4: one warp per dst node. e is recomputed in phase B from the L2-resident
// as[] table (no edge buffer round-trip).
__global__ void gat_node4(const float* __restrict__ h, const float* __restrict__ as,
                          const float* __restrict__ ad, const int* __restrict__ off,
                          const int* __restrict__ csr_src,
                          const float* __restrict__ bias, float* __restrict__ out) {
    int node = (blockIdx.x * blockDim.x + threadIdx.x) >> 5;
    int lane = threadIdx.x & 31;
    if (node >= N_NODES) return;
    int start = off[node], end = off[node + 1];
    float4 adv = ((const float4*)ad)[node];

    // phase A: warp max of e per head
    float4 mx = make_float4(-INFINITY, -INFINITY, -INFINITY, -INFINITY);
    for (int k = start + lane; k < end; k += 32) {
        int s = csr_src[k];
        float4 a = ((const float4*)as)[s];
        mx.x = fmaxf(mx.x, lrelu(a.x + adv.x));
        mx.y = fmaxf(mx.y, lrelu(a.y + adv.y));
        mx.z = fmaxf(mx.z, lrelu(a.z + adv.z));
        mx.w = fmaxf(mx.w, lrelu(a.w + adv.w));
    }
#pragma unroll
    for (int o = 16; o >= 1; o >>= 1) {
        mx.x = fmaxf(mx.x, __shfl_xor_sync(0xffffffffu, mx.x, o));
        mx.y = fmaxf(mx.y, __shfl_xor_sync(0xffffffffu, mx.y, o));
        mx.z = fmaxf(mx.z, __shfl_xor_sync(0xffffffffu, mx.z, o));
        mx.w = fmaxf(mx.w, __shfl_xor_sync(0xffffffffu, mx.w, o));
    }
    __syncwarp();

    // phase B: per-head numerator / denominator
    int head = lane >> 3;
    float mh = head == 0 ? mx.x : head == 1 ? mx.y : head == 2 ? mx.z : mx.w;
    float advh = head == 0 ? adv.x : head == 1 ? adv.y : head == 2 ? adv.z : adv.w;
    float acc[8] = {};
    float den = 0.0f;
    const float4* hb = (const float4*)h;
    for (int k = start; k < end; k++) {
        int s = csr_src[k];
        float eh = lrelu(__ldg(&as[s * 4 + head]) + advh);
        float ex = __expf(eh - mh);
        den += ex;
        const float4* hr = hb + (size_t)s * 64 + lane * 2;
        float4 v0 = hr[0], v1 = hr[1];
        acc[0] += v0.x * ex; acc[1] += v0.y * ex; acc[2] += v0.z * ex; acc[3] += v0.w * ex;
        acc[4] += v1.x * ex; acc[5] += v1.y * ex; acc[6] += v1.z * ex; acc[7] += v1.w * ex;
    }
    float inv = 1.0f / (den + EPS);
    const float* bp = bias + lane * 8;
    float4 o0, o1;
    o0.x = fmaxf(acc[0] * inv + bp[0], 0.f); o0.y = fmaxf(acc[1] * inv + bp[1], 0.f);
    o0.z = fmaxf(acc[2] * inv + bp[2], 0.f); o0.w = fmaxf(acc[3] * inv + bp[3], 0.f);
    o1.x = fmaxf(acc[4] * inv + bp[4], 0.f); o1.y = fmaxf(acc[5] * inv + bp[5], 0.f);
    o1.z = fmaxf(acc[6] * inv + bp[6], 0.f); o1.w = fmaxf(acc[7] * inv + bp[7], 0.f);
    float4* orow = (float4*)(out + (size_t)node * 256) + lane * 2;
    orow[0] = o0;
    orow[1] = o1;
}

// H=1, C=64 final layer: fused softmax+agg+bias+relu+POOL (h3 never materialized)
__global__ void gat_node1_pool(const float* __restrict__ h, const float* __restrict__ as,
                               const float* __restrict__ ad, const int* __restrict__ off,
                               const int* __restrict__ csr_src,
                               const float* __restrict__ bias, const int* __restrict__ batch,
                               float* __restrict__ pool) {
    int node = (blockIdx.x * blockDim.x + threadIdx.x) >> 5;
    int lane = threadIdx.x & 31;
    if (node >= N_NODES) return;
    int start = off[node], end = off[node + 1];
    float adv = ad[node];

    float mx = -INFINITY;
    for (int k = start + lane; k < end; k += 32)
        mx = fmaxf(mx, lrelu(as[csr_src[k]] + adv));
#pragma unroll
    for (int o = 16; o >= 1; o >>= 1)
        mx = fmaxf(mx, __shfl_xor_sync(0xffffffffu, mx, o));
    __syncwarp();

    float acc0 = 0.f, acc1 = 0.f, den = 0.f;
    const float2* hb = (const float2*)h;
    for (int k = start; k < end; k++) {
        int s = csr_src[k];
        float ex = __expf(lrelu(__ldg(&as[s]) + adv) - mx);
        den += ex;
        float2 v = hb[(size_t)s * 32 + lane];
        acc0 += v.x * ex;
        acc1 += v.y * ex;
    }
    float inv = 1.0f / (den + EPS);
    float o0 = fmaxf(acc0 * inv + bias[lane * 2], 0.f);
    float o1 = fmaxf(acc1 * inv + bias[lane * 2 + 1], 0.f);
    int g = batch[node];
    red_add_v2(pool + g * 64 + lane * 2, o0, o1);
    if (lane == 0) atomicAdd(&pool[NG * 64 + g], 1.0f);
}

// ---------------- pooling + classifier ------------------------------------------
__global__ void zero_pool(float* __restrict__ p) {
    int i = blockIdx.x * blockDim.x + threadIdx.x;
    if (i < NG * 64 + NG) p[i] = 0.0f;
}

__global__ void classifier(const float* __restrict__ pool, const float* __restrict__ Wl,
                           const float* __restrict__ bl, float* __restrict__ out) {
    int t = threadIdx.x;
    if (t >= NG * NCLS) return;
    int g = t / NCLS, j = t % NCLS;
    float cnt = fmaxf(pool[NG * 64 + g], 1.0f);
    float s = 0.0f;
#pragma unroll
    for (int c = 0; c < 64; c++) s += pool[g * 64 + c] * Wl[c * NCLS + j];
    out[t] = s / cnt + bl[j];
}

// ---------------- launch --------------------------------------------------------
extern "C" void kernel_launch(void* const* d_in, const int* in_sizes, int n_in,
                              void* d_out, int out_size) {
    const float* x   = (const float*)d_in[0];
    const void*  ei  = d_in[1];
    const void*  bat = d_in[2];
    const float* W1 = (const float*)d_in[3];
    const float* s1 = (const float*)d_in[4];
    const float* t1 = (const float*)d_in[5];
    const float* b1 = (const float*)d_in[6];
    const float* W2 = (const float*)d_in[7];
    const float* s2 = (const float*)d_in[8];
    const float* t2 = (const float*)d_in[9];
    const float* b2 = (const float*)d_in[10];
    const float* W3 = (const float*)d_in[11];
    const float* s3 = (const float*)d_in[12];
    const float* t3 = (const float*)d_in[13];
    const float* b3 = (const float*)d_in[14];
    const float* Wl = (const float*)d_in[15];
    const float* bl = (const float*)d_in[16];
    float* out = (float*)d_out;

    float *A, *B, *AS, *AD, *POOL;
    int *SRC, *DST, *BATCH, *DEG, *INCL, *BSUM, *OFF, *CUR, *CSR;
    cudaGetSymbolAddress((void**)&A, g_bufA);
    cudaGetSymbolAddress((void**)&B, g_bufB);
    cudaGetSymbolAddress((void**)&AS, g_as);
    cudaGetSymbolAddress((void**)&AD, g_ad);
    cudaGetSymbolAddress((void**)&POOL, g_pool);
    cudaGetSymbolAddress((void**)&SRC, g_src);
    cudaGetSymbolAddress((void**)&DST, g_dst);
    cudaGetSymbolAddress((void**)&BATCH, g_batch);
    cudaGetSymbolAddress((void**)&DEG, g_deg);
    cudaGetSymbolAddress((void**)&INCL, g_incl);
    cudaGetSymbolAddress((void**)&BSUM, g_bsum);
    cudaGetSymbolAddress((void**)&OFF, g_off);
    cudaGetSymbolAddress((void**)&CUR, g_cursor);
    cudaGetSymbolAddress((void**)&CSR, g_csr_src);

    const int TB = 256;
    int eThr = (EE + TB - 1) / TB;
    int nThr = (N_NODES + TB - 1) / TB;
    int nWarp = (N_NODES * 32 + TB - 1) / TB;
    int mT128 = (N_NODES + 127) / 128;

    detect_dtypes<<<1, 32>>>(ei, bat);
    build_edges<<<eThr, TB>>>(ei, SRC, DST);
    conv_batch<<<nThr, TB>>>(bat, BATCH);

    // CSR by dst
    zero_deg<<<nThr, TB>>>(DEG);
    hist_dst<<<eThr, TB>>>(DST, DEG);
    scan1<<<NB_SCAN, 256>>>(DEG, INCL, BSUM);
    scan2<<<1, 256>>>(BSUM);
    scan3<<<nThr, TB>>>(DEG, INCL, BSUM, OFF, CUR);
    scatter_csr<<<eThr, TB>>>(SRC, DST, CUR, CSR);

    // ---- layer 1: 128 -> 4x64 concat ----
    mma_gemm<128><<<dim3(2, mT128), TB>>>(x, W1, A, N_NODES, 256, 128);
    dots4<<<nWarp, TB>>>(A, s1, t1, AS, AD);
    gat_node4<<<nWarp, TB>>>(A, AS, AD, OFF, CSR, b1, B);

    // ---- layer 2: 256 -> 4x64 concat ----
    mma_gemm<128><<<dim3(2, mT128), TB>>>(B, W2, A, N_NODES, 256, 256);
    dots4<<<nWarp, TB>>>(A, s2, t2, AS, AD);
    gat_node4<<<nWarp, TB>>>(A, AS, AD, OFF, CSR, b2, B);

    // ---- layer 3: 256 -> 64, heads=1, no concat; fused with pooling ----
    mma_gemm<64><<<dim3(1, mT128), TB>>>(B, W3, A, N_NODES, 64, 256);
    dots1<<<nWarp, TB>>>(A, s3, t3, AS, AD);
    zero_pool<<<(NG * 64 + NG + TB - 1) / TB, TB>>>(POOL);
    gat_node1_pool<<<nWarp, TB>>>(A, AS, AD, OFF, CSR, b3, BATCH, POOL);

    classifier<<<1, 640>>>(POOL, Wl, bl, out);
}

// round 7
// speedup vs baseline: 2.7340x; 1.0262x over previous
#include <cuda_runtime.h>
#include <cstdint>

#define N_NODES 50000
#define N_EDGES 800000
#define EE (N_EDGES + N_NODES)   // edges + self loops = 850000
#define NG 64
#define NCLS 10
#define NEG_SLOPE 0.2f
#define EPS 1e-16f
#define NB_SCAN ((N_NODES + 255) / 256)

// ---------------- scratch (static device globals; no runtime alloc) -------------
__device__ __align__(16) float g_bufA[N_NODES * 256];
__device__ __align__(16) float g_bufB[N_NODES * 256];
__device__ __align__(16) float g_as[N_NODES * 4];
__device__ __align__(16) float g_ad[N_NODES * 4];
__device__ __align__(16) int   g_src[EE];
__device__ __align__(16) int   g_dst[EE];
__device__ __align__(16) int   g_batch[N_NODES];
__device__ __align__(16) int   g_deg[N_NODES];
__device__ __align__(16) int   g_incl[N_NODES];
__device__ __align__(16) int   g_bsum[256];
__device__ __align__(16) int   g_off[N_NODES + 1];
__device__ __align__(16) int   g_cursor[N_NODES];
__device__ __align__(16) int   g_csr_src[EE];
__device__ __align__(16) float g_pool[NG * 64 + NG];
__device__ int g_flags[2];

// ---------------- helpers -------------------------------------------------------
__device__ __forceinline__ void red_add_v2(float* addr, float a, float b) {
    asm volatile("red.global.add.v2.f32 [%0], {%1,%2};"
                 :: "l"(addr), "f"(a), "f"(b) : "memory");
}
__device__ __forceinline__ float lrelu(float v) { return v >= 0.0f ? v : NEG_SLOPE * v; }

__device__ __forceinline__ float f2tf32(float x) {
    uint32_t r;
    asm("cvt.rna.tf32.f32 %0, %1;" : "=r"(r) : "f"(x));
    return __uint_as_float(r);
}

__device__ __forceinline__ void mma_tf32(float* d, uint32_t a0, uint32_t a1,
                                         uint32_t a2, uint32_t a3,
                                         uint32_t b0, uint32_t b1) {
    asm("mma.sync.aligned.m16n8k8.row.col.f32.tf32.tf32.f32 "
        "{%0,%1,%2,%3},{%4,%5,%6,%7},{%8,%9},{%0,%1,%2,%3};"
        : "+f"(d[0]), "+f"(d[1]), "+f"(d[2]), "+f"(d[3])
        : "r"(a0), "r"(a1), "r"(a2), "r"(a3), "r"(b0), "r"(b1));
}

// ---------------- prep: dtype detect + zero deg + zero pool ---------------------
__global__ void prep(const void* ei, const void* bat, int* __restrict__ deg,
                     float* __restrict__ pool) {
    int i = blockIdx.x * blockDim.x + threadIdx.x;
    if (i == 0) {
        const long long* e64 = (const long long*)ei;
        int ok = 1;
        for (int j = 0; j < 8; j++) {
            long long v = e64[j];
            if (v < 0 || v >= N_NODES) ok = 0;
        }
        g_flags[0] = ok;
        const long long* b64 = (const long long*)bat;
        int okb = 1;
        for (int j = 0; j < 8; j++) {
            long long v = b64[N_NODES / 2 - 1 - j];
            if (v < 0 || v >= NG) okb = 0;
        }
        g_flags[1] = okb;
    }
    if (i < N_NODES) deg[i] = 0;
    if (i < NG * 64 + NG) pool[i] = 0.0f;
}

// ---------------- build edges + degree histogram + batch convert ----------------
__global__ void build_hist(const void* ei, const void* bat, int* __restrict__ src,
                           int* __restrict__ dst, int* __restrict__ deg,
                           int* __restrict__ batch) {
    int i = blockIdx.x * blockDim.x + threadIdx.x;
    if (i < EE) {
        int s, d;
        if (i < N_EDGES) {
            if (g_flags[0]) {
                const long long* e = (const long long*)ei;
                s = (int)e[i];
                d = (int)e[N_EDGES + i];
            } else {
                const int* e = (const int*)ei;
                s = e[i];
                d = e[N_EDGES + i];
            }
        } else {
            s = d = i - N_EDGES;
        }
        src[i] = s;
        dst[i] = d;
        atomicAdd(&deg[d], 1);
    }
    if (i < N_NODES) {
        if (g_flags[1]) batch[i] = (int)((const long long*)bat)[i];
        else            batch[i] = ((const int*)bat)[i];
    }
}

// ---------------- CSR scan + scatter --------------------------------------------
__global__ void scan1(const int* __restrict__ deg, int* __restrict__ incl,
                      int* __restrict__ bsum) {
    __shared__ int s[256];
    int t = threadIdx.x;
    int i = blockIdx.x * 256 + t;
    int v = (i < N_NODES) ? deg[i] : 0;
    s[t] = v;
    __syncthreads();
#pragma unroll
    for (int o = 1; o < 256; o <<= 1) {
        int x = (t >= o) ? s[t - o] : 0;
        __syncthreads();
        s[t] += x;
        __syncthreads();
    }
    if (i < N_NODES) incl[i] = s[t];
    if (t == 255) bsum[blockIdx.x] = s[255];
}

__global__ void scan2(int* __restrict__ bsum) {
    __shared__ int s[256];
    int t = threadIdx.x;
    int v = (t < NB_SCAN) ? bsum[t] : 0;
    s[t] = v;
    __syncthreads();
#pragma unroll
    for (int o = 1; o < 256; o <<= 1) {
        int x = (t >= o) ? s[t - o] : 0;
        __syncthreads();
        s[t] += x;
        __syncthreads();
    }
    bsum[t] = s[t] - v;
}

__global__ void scan3(const int* __restrict__ deg, const int* __restrict__ incl,
                      const int* __restrict__ bsum, int* __restrict__ off,
                      int* __restrict__ cursor) {
    int i = blockIdx.x * blockDim.x + threadIdx.x;
    if (i >= N_NODES) return;
    int o = incl[i] - deg[i] + bsum[i >> 8];
    off[i] = o;
    cursor[i] = o;
    if (i == 0) off[N_NODES] = EE;
}

__global__ void scatter_csr(const int* __restrict__ src, const int* __restrict__ dst,
                            int* __restrict__ cursor, int* __restrict__ csr_src) {
    int i = blockIdx.x * blockDim.x + threadIdx.x;
    if (i >= EE) return;
    int pos = atomicAdd(&cursor[dst[i]], 1);
    csr_src[pos] = src[i];
}

// ---------------- TF32 tensor-core GEMM -----------------------------------------
// C[M,N] = A[M,K] @ B[K,N]; BM=128, BN template (128 or 64), BK=16.
// 256 threads = 8 warps in 2(M) x 4(N); warp tile 64 x (BN/4).
template <int BN>
__global__ void mma_gemm(const float* __restrict__ A, const float* __restrict__ Bm,
                         float* __restrict__ C, int M, int N, int K) {
    constexpr int WN = BN / 4;
    constexpr int NT = WN / 8;
    __shared__ float As[16][136];
    __shared__ float Bs[16][BN + 8];
    int tid = threadIdx.x;
    int lane = tid & 31, warp = tid >> 5;
    int wm = (warp & 1) * 64, wn = (warp >> 1) * WN;
    int m0 = blockIdx.y * 128, n0 = blockIdx.x * BN;
    int l3 = lane & 3, l2 = lane >> 2;

    float acc[4][NT][4] = {};

    for (int k0 = 0; k0 < K; k0 += 16) {
#pragma unroll
        for (int i = 0; i < 2; i++) {
            int f = tid * 2 + i;
            int row = f >> 2, c4 = (f & 3) << 2;
            float4 av = make_float4(0.f, 0.f, 0.f, 0.f);
            if (m0 + row < M)
                av = *(const float4*)(A + (size_t)(m0 + row) * K + k0 + c4);
            As[c4 + 0][row] = f2tf32(av.x);
            As[c4 + 1][row] = f2tf32(av.y);
            As[c4 + 2][row] = f2tf32(av.z);
            As[c4 + 3][row] = f2tf32(av.w);
        }
        if (BN == 128) {
#pragma unroll
            for (int i = 0; i < 2; i++) {
                int f = tid * 2 + i;
                int row = f >> 5, c4 = (f & 31) << 2;
                float4 bv = *(const float4*)(Bm + (size_t)(k0 + row) * N + n0 + c4);
                Bs[row][c4 + 0] = f2tf32(bv.x);
                Bs[row][c4 + 1] = f2tf32(bv.y);
                Bs[row][c4 + 2] = f2tf32(bv.z);
                Bs[row][c4 + 3] = f2tf32(bv.w);
            }
        } else {
            int row = tid >> 4, c4 = (tid & 15) << 2;
            float4 bv = *(const float4*)(Bm + (size_t)(k0 + row) * N + n0 + c4);
            Bs[row][c4 + 0] = f2tf32(bv.x);
            Bs[row][c4 + 1] = f2tf32(bv.y);
            Bs[row][c4 + 2] = f2tf32(bv.z);
            Bs[row][c4 + 3] = f2tf32(bv.w);
        }
        __syncthreads();

#pragma unroll
        for (int kk = 0; kk < 16; kk += 8) {
            uint32_t bf[NT][2];
#pragma unroll
            for (int j = 0; j < NT; j++) {
                bf[j][0] = __float_as_uint(Bs[kk + l3][wn + j * 8 + l2]);
                bf[j][1] = __float_as_uint(Bs[kk + l3 + 4][wn + j * 8 + l2]);
            }
#pragma unroll
            for (int i = 0; i < 4; i++) {
                uint32_t a0 = __float_as_uint(As[kk + l3][wm + i * 16 + l2]);
                uint32_t a1 = __float_as_uint(As[kk + l3][wm + i * 16 + l2 + 8]);
                uint32_t a2 = __float_as_uint(As[kk + l3 + 4][wm + i * 16 + l2]);
                uint32_t a3 = __float_as_uint(As[kk + l3 + 4][wm + i * 16 + l2 + 8]);
#pragma unroll
                for (int j = 0; j < NT; j++)
                    mma_tf32(acc[i][j], a0, a1, a2, a3, bf[j][0], bf[j][1]);
            }
        }
        __syncthreads();
    }

#pragma unroll
    for (int i = 0; i < 4; i++) {
#pragma unroll
        for (int j = 0; j < NT; j++) {
            int r0 = m0 + wm + i * 16 + l2;
            int c = n0 + wn + j * 8 + 2 * l3;
            if (r0 < M)
                *(float2*)(C + (size_t)r0 * N + c) = make_float2(acc[i][j][0], acc[i][j][1]);
            if (r0 + 8 < M)
                *(float2*)(C + (size_t)(r0 + 8) * N + c) = make_float2(acc[i][j][2], acc[i][j][3]);
        }
    }
}

// ---------------- attention dot products (per node) -----------------------------
__global__ void dots4(const float* __restrict__ h, const float* __restrict__ a_src,
                      const float* __restrict__ a_dst, float* __restrict__ as,
                      float* __restrict__ ad) {
    int warp = (blockIdx.x * blockDim.x + threadIdx.x) >> 5;
    int lane = threadIdx.x & 31;
    if (warp >= N_NODES) return;
    const float4* hr = (const float4*)(h + (size_t)warp * 256);
    const float4* sr = (const float4*)a_src;
    const float4* dr = (const float4*)a_dst;
    float4 h0 = hr[lane * 2], h1 = hr[lane * 2 + 1];
    float4 s0 = sr[lane * 2], s1 = sr[lane * 2 + 1];
    float4 d0 = dr[lane * 2], d1 = dr[lane * 2 + 1];
    float ps = h0.x * s0.x + h0.y * s0.y + h0.z * s0.z + h0.w * s0.w +
               h1.x * s1.x + h1.y * s1.y + h1.z * s1.z + h1.w * s1.w;
    float pd = h0.x * d0.x + h0.y * d0.y + h0.z * d0.z + h0.w * d0.w +
               h1.x * d1.x + h1.y * d1.y + h1.z * d1.z + h1.w * d1.w;
#pragma unroll
    for (int o = 4; o >= 1; o >>= 1) {
        ps += __shfl_down_sync(0xffffffffu, ps, o, 8);
        pd += __shfl_down_sync(0xffffffffu, pd, o, 8);
    }
    if ((lane & 7) == 0) {
        int hd = lane >> 3;
        as[warp * 4 + hd] = ps;
        ad[warp * 4 + hd] = pd;
    }
}

__global__ void dots1(const float* __restrict__ h, const float* __restrict__ a_src,
                      const float* __restrict__ a_dst, float* __restrict__ as,
                      float* __restrict__ ad) {
    int warp = (blockIdx.x * blockDim.x + threadIdx.x) >> 5;
    int lane = threadIdx.x & 31;
    if (warp >= N_NODES) return;
    float2 hv = ((const float2*)(h + (size_t)warp * 64))[lane];
    float2 sv = ((const float2*)a_src)[lane];
    float2 dv = ((const float2*)a_dst)[lane];
    float ps = hv.x * sv.x + hv.y * sv.y;
    float pd = hv.x * dv.x + hv.y * dv.y;
#pragma unroll
    for (int o = 16; o >= 1; o >>= 1) {
        ps += __shfl_down_sync(0xffffffffu, ps, o);
        pd += __shfl_down_sync(0xffffffffu, pd, o);
    }
    if (lane == 0) {
        as[warp] = ps;
        ad[warp] = pd;
    }
}

// ---------------- fused GAT layer (softmax + aggregate + bias + relu) -----------
// H=4: one warp per dst node; phase-B edge loop unrolled x2 for gather MLP.
__global__ void gat_node4(const float* __restrict__ h, const float* __restrict__ as,
                          const float* __restrict__ ad, const int* __restrict__ off,
                          const int* __restrict__ csr_src,
                          const float* __restrict__ bias, float* __restrict__ out) {
    int node = (blockIdx.x * blockDim.x + threadIdx.x) >> 5;
    int lane = threadIdx.x & 31;
    if (node >= N_NODES) return;
    int start = off[node], end = off[node + 1];
    float4 adv = ((const float4*)ad)[node];

    // phase A: warp max of e per head
    float4 mx = make_float4(-INFINITY, -INFINITY, -INFINITY, -INFINITY);
    for (int k = start + lane; k < end; k += 32) {
        int s = __ldg(&csr_src[k]);
        float4 a = __ldg((const float4*)as + s);
        mx.x = fmaxf(mx.x, lrelu(a.x + adv.x));
        mx.y = fmaxf(mx.y, lrelu(a.y + adv.y));
        mx.z = fmaxf(mx.z, lrelu(a.z + adv.z));
        mx.w = fmaxf(mx.w, lrelu(a.w + adv.w));
    }
#pragma unroll
    for (int o = 16; o >= 1; o >>= 1) {
        mx.x = fmaxf(mx.x, __shfl_xor_sync(0xffffffffu, mx.x, o));
        mx.y = fmaxf(mx.y, __shfl_xor_sync(0xffffffffu, mx.y, o));
        mx.z = fmaxf(mx.z, __shfl_xor_sync(0xffffffffu, mx.z, o));
        mx.w = fmaxf(mx.w, __shfl_xor_sync(0xffffffffu, mx.w, o));
    }
    __syncwarp();

    // phase B: per-head numerator / denominator, unrolled x2
    int head = lane >> 3;
    float mh = head == 0 ? mx.x : head == 1 ? mx.y : head == 2 ? mx.z : mx.w;
    float advh = head == 0 ? adv.x : head == 1 ? adv.y : head == 2 ? adv.z : adv.w;
    float acc[8] = {};
    float den = 0.0f;
    const float4* hb = (const float4*)h;
    int k = start;
    for (; k + 2 <= end; k += 2) {
        int s0 = __ldg(&csr_src[k]);
        int s1 = __ldg(&csr_src[k + 1]);
        float as0 = __ldg(&as[s0 * 4 + head]);
        float as1 = __ldg(&as[s1 * 4 + head]);
        const float4* hr0 = hb + (size_t)s0 * 64 + lane * 2;
        const float4* hr1 = hb + (size_t)s1 * 64 + lane * 2;
        float4 u0 = hr0[0], u1 = hr0[1];
        float4 w0 = hr1[0], w1 = hr1[1];
        float ex0 = __expf(lrelu(as0 + advh) - mh);
        float ex1 = __expf(lrelu(as1 + advh) - mh);
        den += ex0 + ex1;
        acc[0] += u0.x * ex0 + w0.x * ex1;
        acc[1] += u0.y * ex0 + w0.y * ex1;
        acc[2] += u0.z * ex0 + w0.z * ex1;
        acc[3] += u0.w * ex0 + w0.w * ex1;
        acc[4] += u1.x * ex0 + w1.x * ex1;
        acc[5] += u1.y * ex0 + w1.y * ex1;
        acc[6] += u1.z * ex0 + w1.z * ex1;
        acc[7] += u1.w * ex0 + w1.w * ex1;
    }
    if (k < end) {
        int s = __ldg(&csr_src[k]);
        float ex = __expf(lrelu(__ldg(&as[s * 4 + head]) + advh) - mh);
        den += ex;
        const float4* hr = hb + (size_t)s * 64 + lane * 2;
        float4 v0 = hr[0], v1 = hr[1];
        acc[0] += v0.x * ex; acc[1] += v0.y * ex; acc[2] += v0.z * ex; acc[3] += v0.w * ex;
        acc[4] += v1.x * ex; acc[5] += v1.y * ex; acc[6] += v1.z * ex; acc[7] += v1.w * ex;
    }
    float inv = 1.0f / (den + EPS);
    const float* bp = bias + lane * 8;
    float4 o0, o1;
    o0.x = fmaxf(acc[0] * inv + bp[0], 0.f); o0.y = fmaxf(acc[1] * inv + bp[1], 0.f);
    o0.z = fmaxf(acc[2] * inv + bp[2], 0.f); o0.w = fmaxf(acc[3] * inv + bp[3], 0.f);
    o1.x = fmaxf(acc[4] * inv + bp[4], 0.f); o1.y = fmaxf(acc[5] * inv + bp[5], 0.f);
    o1.z = fmaxf(acc[6] * inv + bp[6], 0.f); o1.w = fmaxf(acc[7] * inv + bp[7], 0.f);
    float4* orow = (float4*)(out + (size_t)node * 256) + lane * 2;
    orow[0] = o0;
    orow[1] = o1;
}

// H=1, C=64 final layer: fused softmax+agg+bias+relu+POOL, unrolled x2
__global__ void gat_node1_pool(const float* __restrict__ h, const float* __restrict__ as,
                               const float* __restrict__ ad, const int* __restrict__ off,
                               const int* __restrict__ csr_src,
                               const float* __restrict__ bias, const int* __restrict__ batch,
                               float* __restrict__ pool) {
    int node = (blockIdx.x * blockDim.x + threadIdx.x) >> 5;
    int lane = threadIdx.x & 31;
    if (node >= N_NODES) return;
    int start = off[node], end = off[node + 1];
    float adv = ad[node];

    float mx = -INFINITY;
    for (int k = start + lane; k < end; k += 32)
        mx = fmaxf(mx, lrelu(__ldg(&as[__ldg(&csr_src[k])]) + adv));
#pragma unroll
    for (int o = 16; o >= 1; o >>= 1)
        mx = fmaxf(mx, __shfl_xor_sync(0xffffffffu, mx, o));
    __syncwarp();

    float acc0 = 0.f, acc1 = 0.f, den = 0.f;
    const float2* hb = (const float2*)h;
    int k = start;
    for (; k + 2 <= end; k += 2) {
        int s0 = __ldg(&csr_src[k]);
        int s1 = __ldg(&csr_src[k + 1]);
        float a0 = __ldg(&as[s0]);
        float a1 = __ldg(&as[s1]);
        float2 v0 = hb[(size_t)s0 * 32 + lane];
        float2 v1 = hb[(size_t)s1 * 32 + lane];
        float ex0 = __expf(lrelu(a0 + adv) - mx);
        float ex1 = __expf(lrelu(a1 + adv) - mx);
        den += ex0 + ex1;
        acc0 += v0.x * ex0 + v1.x * ex1;
        acc1 += v0.y * ex0 + v1.y * ex1;
    }
    if (k < end) {
        int s = __ldg(&csr_src[k]);
        float ex = __expf(lrelu(__ldg(&as[s]) + adv) - mx);
        den += ex;
        float2 v = hb[(size_t)s * 32 + lane];
        acc0 += v.x * ex;
        acc1 += v.y * ex;
    }
    float inv = 1.0f / (den + EPS);
    float o0 = fmaxf(acc0 * inv + bias[lane * 2], 0.f);
    float o1 = fmaxf(acc1 * inv + bias[lane * 2 + 1], 0.f);
    int g = batch[node];
    red_add_v2(pool + g * 64 + lane * 2, o0, o1);
    if (lane == 0) atomicAdd(&pool[NG * 64 + g], 1.0f);
}

// ---------------- classifier -----------------------------------------------------
__global__ void classifier(const float* __restrict__ pool, const float* __restrict__ Wl,
                           const float* __restrict__ bl, float* __restrict__ out) {
    int t = threadIdx.x;
    if (t >= NG * NCLS) return;
    int g = t / NCLS, j = t % NCLS;
    float cnt = fmaxf(pool[NG * 64 + g], 1.0f);
    float s = 0.0f;
#pragma unroll
    for (int c = 0; c < 64; c++) s += pool[g * 64 + c] * Wl[c * NCLS + j];
    out[t] = s / cnt + bl[j];
}

// ---------------- launch --------------------------------------------------------
extern "C" void kernel_launch(void* const* d_in, const int* in_sizes, int n_in,
                              void* d_out, int out_size) {
    const float* x   = (const float*)d_in[0];
    const void*  ei  = d_in[1];
    const void*  bat = d_in[2];
    const float* W1 = (const float*)d_in[3];
    const float* s1 = (const float*)d_in[4];
    const float* t1 = (const float*)d_in[5];
    const float* b1 = (const float*)d_in[6];
    const float* W2 = (const float*)d_in[7];
    const float* s2 = (const float*)d_in[8];
    const float* t2 = (const float*)d_in[9];
    const float* b2 = (const float*)d_in[10];
    const float* W3 = (const float*)d_in[11];
    const float* s3 = (const float*)d_in[12];
    const float* t3 = (const float*)d_in[13];
    const float* b3 = (const float*)d_in[14];
    const float* Wl = (const float*)d_in[15];
    const float* bl = (const float*)d_in[16];
    float* out = (float*)d_out;

    float *A, *B, *AS, *AD, *POOL;
    int *SRC, *DST, *BATCH, *DEG, *INCL, *BSUM, *OFF, *CUR, *CSR;
    cudaGetSymbolAddress((void**)&A, g_bufA);
    cudaGetSymbolAddress((void**)&B, g_bufB);
    cudaGetSymbolAddress((void**)&AS, g_as);
    cudaGetSymbolAddress((void**)&AD, g_ad);
    cudaGetSymbolAddress((void**)&POOL, g_pool);
    cudaGetSymbolAddress((void**)&SRC, g_src);
    cudaGetSymbolAddress((void**)&DST, g_dst);
    cudaGetSymbolAddress((void**)&BATCH, g_batch);
    cudaGetSymbolAddress((void**)&DEG, g_deg);
    cudaGetSymbolAddress((void**)&INCL, g_incl);
    cudaGetSymbolAddress((void**)&BSUM, g_bsum);
    cudaGetSymbolAddress((void**)&OFF, g_off);
    cudaGetSymbolAddress((void**)&CUR, g_cursor);
    cudaGetSymbolAddress((void**)&CSR, g_csr_src);

    const int TB = 256;
    int eThr = (EE + TB - 1) / TB;
    int nThr = (N_NODES + TB - 1) / TB;
    int nWarp = (N_NODES * 32 + TB - 1) / TB;
    int mT128 = (N_NODES + 127) / 128;

    prep<<<nThr, TB>>>(ei, bat, DEG, POOL);
    build_hist<<<eThr, TB>>>(ei, bat, SRC, DST, DEG, BATCH);
    scan1<<<NB_SCAN, 256>>>(DEG, INCL, BSUM);
    scan2<<<1, 256>>>(BSUM);
    scan3<<<nThr, TB>>>(DEG, INCL, BSUM, OFF, CUR);
    scatter_csr<<<eThr, TB>>>(SRC, DST, CUR, CSR);

    // ---- layer 1: 128 -> 4x64 concat ----
    mma_gemm<128><<<dim3(2, mT128), TB>>>(x, W1, A, N_NODES, 256, 128);
    dots4<<<nWarp, TB>>>(A, s1, t1, AS, AD);
    gat_node4<<<nWarp, TB>>>(A, AS, AD, OFF, CSR, b1, B);

    // ---- layer 2: 256 -> 4x64 concat ----
    mma_gemm<128><<<dim3(2, mT128), TB>>>(B, W2, A, N_NODES, 256, 256);
    dots4<<<nWarp, TB>>>(A, s2, t2, AS, AD);
    gat_node4<<<nWarp, TB>>>(A, AS, AD, OFF, CSR, b2, B);

    // ---- layer 3: 256 -> 64, heads=1, no concat; fused with pooling ----
    mma_gemm<64><<<dim3(1, mT128), TB>>>(B, W3, A, N_NODES, 64, 256);
    dots1<<<nWarp, TB>>>(A, s3, t3, AS, AD);
    gat_node1_pool<<<nWarp, TB>>>(A, AS, AD, OFF, CSR, b3, BATCH, POOL);

    classifier<<<1, 640>>>(POOL, Wl, bl, out);
}

// round 9
// speedup vs baseline: 3.0735x; 1.1242x over previous
#include <cuda_runtime.h>
#include <cuda_fp16.h>
#include <cstdint>

#define N_NODES 50000
#define N_EDGES 800000
#define EE (N_EDGES + N_NODES)   // edges + self loops = 850000
#define NG 64
#define NCLS 10
#define NEG_SLOPE 0.2f
#define EPS 1e-16f
#define NB_SCAN ((N_NODES + 255) / 256)

// ---------------- scratch (static device globals; no runtime alloc) -------------
__device__ __align__(16) float  g_bufA[N_NODES * 256];
__device__ __align__(16) float  g_bufB[N_NODES * 256];
__device__ __align__(16) __half g_h16[N_NODES * 256];   // fp16 copy of h for gathers
__device__ __align__(16) float  g_as[N_NODES * 4];
__device__ __align__(16) float  g_ad[N_NODES * 4];
__device__ __align__(16) int    g_src[EE];
__device__ __align__(16) int    g_dst[EE];
__device__ __align__(16) int    g_batch[N_NODES];
__device__ __align__(16) int    g_deg[N_NODES];
__device__ __align__(16) int    g_incl[N_NODES];
__device__ __align__(16) int    g_bsum[256];
__device__ __align__(16) int    g_off[N_NODES + 1];
__device__ __align__(16) int    g_cursor[N_NODES];
__device__ __align__(16) int    g_csr_src[EE];
__device__ __align__(16) float  g_pool[NG * 64 + NG];
__device__ int g_flags[2];

// ---------------- helpers -------------------------------------------------------
__device__ __forceinline__ void red_add_v2(float* addr, float a, float b) {
    asm volatile("red.global.add.v2.f32 [%0], {%1,%2};"
                 :: "l"(addr), "f"(a), "f"(b) : "memory");
}
__device__ __forceinline__ float lrelu(float v) { return v >= 0.0f ? v : NEG_SLOPE * v; }

__device__ __forceinline__ float f2tf32(float x) {
    uint32_t r;
    asm("cvt.rna.tf32.f32 %0, %1;" : "=r"(r) : "f"(x));
    return __uint_as_float(r);
}

__device__ __forceinline__ void mma_tf32(float* d, uint32_t a0, uint32_t a1,
                                         uint32_t a2, uint32_t a3,
                                         uint32_t b0, uint32_t b1) {
    asm("mma.sync.aligned.m16n8k8.row.col.f32.tf32.tf32.f32 "
        "{%0,%1,%2,%3},{%4,%5,%6,%7},{%8,%9},{%0,%1,%2,%3};"
        : "+f"(d[0]), "+f"(d[1]), "+f"(d[2]), "+f"(d[3])
        : "r"(a0), "r"(a1), "r"(a2), "r"(a3), "r"(b0), "r"(b1));
}

__device__ __forceinline__ uint32_t pack_h2(float a, float b) {
    __half2 h = __floats2half2_rn(a, b);
    return *(uint32_t*)&h;
}
__device__ __forceinline__ float2 unpack_h2(uint32_t u) {
    return __half22float2(*(__half2*)&u);
}

// ---------------- prep: dtype detect + zero deg + zero pool ---------------------
__global__ void prep(const void* ei, const void* bat, int* __restrict__ deg,
                     float* __restrict__ pool) {
    int i = blockIdx.x * blockDim.x + threadIdx.x;
    if (i == 0) {
        const long long* e64 = (const long long*)ei;
        int ok = 1;
        for (int j = 0; j < 8; j++) {
            long long v = e64[j];
            if (v < 0 || v >= N_NODES) ok = 0;
        }
        g_flags[0] = ok;
        const long long* b64 = (const long long*)bat;
        int okb = 1;
        for (int j = 0; j < 8; j++) {
            long long v = b64[N_NODES / 2 - 1 - j];
            if (v < 0 || v >= NG) okb = 0;
        }
        g_flags[1] = okb;
    }
    if (i < N_NODES) deg[i] = 0;
    if (i < NG * 64 + NG) pool[i] = 0.0f;
}

// ---------------- build edges + degree histogram + batch convert ----------------
__global__ void build_hist(const void* ei, const void* bat, int* __restrict__ src,
                           int* __restrict__ dst, int* __restrict__ deg,
                           int* __restrict__ batch) {
    int i = blockIdx.x * blockDim.x + threadIdx.x;
    if (i < EE) {
        int s, d;
        if (i < N_EDGES) {
            if (g_flags[0]) {
                const long long* e = (const long long*)ei;
                s = (int)e[i];
                d = (int)e[N_EDGES + i];
            } else {
                const int* e = (const int*)ei;
                s = e[i];
                d = e[N_EDGES + i];
            }
        } else {
            s = d = i - N_EDGES;
        }
        src[i] = s;
        dst[i] = d;
        atomicAdd(&deg[d], 1);
    }
    if (i < N_NODES) {
        if (g_flags[1]) batch[i] = (int)((const long long*)bat)[i];
        else            batch[i] = ((const int*)bat)[i];
    }
}

// ---------------- CSR scan + scatter --------------------------------------------
__global__ void scan1(const int* __restrict__ deg, int* __restrict__ incl,
                      int* __restrict__ bsum) {
    __shared__ int s[256];
    int t = threadIdx.x;
    int i = blockIdx.x * 256 + t;
    int v = (i < N_NODES) ? deg[i] : 0;
    s[t] = v;
    __syncthreads();
#pragma unroll
    for (int o = 1; o < 256; o <<= 1) {
        int x = (t >= o) ? s[t - o] : 0;
        __syncthreads();
        s[t] += x;
        __syncthreads();
    }
    if (i < N_NODES) incl[i] = s[t];
    if (t == 255) bsum[blockIdx.x] = s[255];
}

__global__ void scan2(int* __restrict__ bsum) {
    __shared__ int s[256];
    int t = threadIdx.x;
    int v = (t < NB_SCAN) ? bsum[t] : 0;
    s[t] = v;
    __syncthreads();
#pragma unroll
    for (int o = 1; o < 256; o <<= 1) {
        int x = (t >= o) ? s[t - o] : 0;
        __syncthreads();
        s[t] += x;
        __syncthreads();
    }
    bsum[t] = s[t] - v;
}

__global__ void scan3(const int* __restrict__ deg, const int* __restrict__ incl,
                      const int* __restrict__ bsum, int* __restrict__ off,
                      int* __restrict__ cursor) {
    int i = blockIdx.x * blockDim.x + threadIdx.x;
    if (i >= N_NODES) return;
    int o = incl[i] - deg[i] + bsum[i >> 8];
    off[i] = o;
    cursor[i] = o;
    if (i == 0) off[N_NODES] = EE;
}

__global__ void scatter_csr(const int* __restrict__ src, const int* __restrict__ dst,
                            int* __restrict__ cursor, int* __restrict__ csr_src) {
    int i = blockIdx.x * blockDim.x + threadIdx.x;
    if (i >= EE) return;
    int pos = atomicAdd(&cursor[dst[i]], 1);
    csr_src[pos] = src[i];
}

// ---------------- TF32 tensor-core GEMM -----------------------------------------
template <int BN>
__global__ void mma_gemm(const float* __restrict__ A, const float* __restrict__ Bm,
                         float* __restrict__ C, int M, int N, int K) {
    constexpr int WN = BN / 4;
    constexpr int NT = WN / 8;
    __shared__ float As[16][136];
    __shared__ float Bs[16][BN + 8];
    int tid = threadIdx.x;
    int lane = tid & 31, warp = tid >> 5;
    int wm = (warp & 1) * 64, wn = (warp >> 1) * WN;
    int m0 = blockIdx.y * 128, n0 = blockIdx.x * BN;
    int l3 = lane & 3, l2 = lane >> 2;

    float acc[4][NT][4] = {};

    for (int k0 = 0; k0 < K; k0 += 16) {
#pragma unroll
        for (int i = 0; i < 2; i++) {
            int f = tid * 2 + i;
            int row = f >> 2, c4 = (f & 3) << 2;
            float4 av = make_float4(0.f, 0.f, 0.f, 0.f);
            if (m0 + row < M)
                av = *(const float4*)(A + (size_t)(m0 + row) * K + k0 + c4);
            As[c4 + 0][row] = f2tf32(av.x);
            As[c4 + 1][row] = f2tf32(av.y);
            As[c4 + 2][row] = f2tf32(av.z);
            As[c4 + 3][row] = f2tf32(av.w);
        }
        if (BN == 128) {
#pragma unroll
            for (int i = 0; i < 2; i++) {
                int f = tid * 2 + i;
                int row = f >> 5, c4 = (f & 31) << 2;
                float4 bv = *(const float4*)(Bm + (size_t)(k0 + row) * N + n0 + c4);
                Bs[row][c4 + 0] = f2tf32(bv.x);
                Bs[row][c4 + 1] = f2tf32(bv.y);
                Bs[row][c4 + 2] = f2tf32(bv.z);
                Bs[row][c4 + 3] = f2tf32(bv.w);
            }
        } else {
            int row = tid >> 4, c4 = (tid & 15) << 2;
            float4 bv = *(const float4*)(Bm + (size_t)(k0 + row) * N + n0 + c4);
            Bs[row][c4 + 0] = f2tf32(bv.x);
            Bs[row][c4 + 1] = f2tf32(bv.y);
            Bs[row][c4 + 2] = f2tf32(bv.z);
            Bs[row][c4 + 3] = f2tf32(bv.w);
        }
        __syncthreads();

#pragma unroll
        for (int kk = 0; kk < 16; kk += 8) {
            uint32_t bf[NT][2];
#pragma unroll
            for (int j = 0; j < NT; j++) {
                bf[j][0] = __float_as_uint(Bs[kk + l3][wn + j * 8 + l2]);
                bf[j][1] = __float_as_uint(Bs[kk + l3 + 4][wn + j * 8 + l2]);
            }
#pragma unroll
            for (int i = 0; i < 4; i++) {
                uint32_t a0 = __float_as_uint(As[kk + l3][wm + i * 16 + l2]);
                uint32_t a1 = __float_as_uint(As[kk + l3][wm + i * 16 + l2 + 8]);
                uint32_t a2 = __float_as_uint(As[kk + l3 + 4][wm + i * 16 + l2]);
                uint32_t a3 = __float_as_uint(As[kk + l3 + 4][wm + i * 16 + l2 + 8]);
#pragma unroll
                for (int j = 0; j < NT; j++)
                    mma_tf32(acc[i][j], a0, a1, a2, a3, bf[j][0], bf[j][1]);
            }
        }
        __syncthreads();
    }

#pragma unroll
    for (int i = 0; i < 4; i++) {
#pragma unroll
        for (int j = 0; j < NT; j++) {
            int r0 = m0 + wm + i * 16 + l2;
            int c = n0 + wn + j * 8 + 2 * l3;
            if (r0 < M)
                *(float2*)(C + (size_t)r0 * N + c) = make_float2(acc[i][j][0], acc[i][j][1]);
            if (r0 + 8 < M)
                *(float2*)(C + (size_t)(r0 + 8) * N + c) = make_float2(acc[i][j][2], acc[i][j][3]);
        }
    }
}

// ---------------- attention dots + fp16 message emit (per node) ------------------
__global__ void dots4(const float* __restrict__ h, const float* __restrict__ a_src,
                      const float* __restrict__ a_dst, float* __restrict__ as,
                      float* __restrict__ ad, __half* __restrict__ h16) {
    int warp = (blockIdx.x * blockDim.x + threadIdx.x) >> 5;
    int lane = threadIdx.x & 31;
    if (warp >= N_NODES) return;
    const float4* hr = (const float4*)(h + (size_t)warp * 256);
    const float4* sr = (const float4*)a_src;
    const float4* dr = (const float4*)a_dst;
    float4 h0 = hr[lane * 2], h1 = hr[lane * 2 + 1];
    float4 s0 = sr[lane * 2], s1 = sr[lane * 2 + 1];
    float4 d0 = dr[lane * 2], d1 = dr[lane * 2 + 1];
    // emit fp16 copy for the gather phase
    uint4 p;
    p.x = pack_h2(h0.x, h0.y);
    p.y = pack_h2(h0.z, h0.w);
    p.z = pack_h2(h1.x, h1.y);
    p.w = pack_h2(h1.z, h1.w);
    ((uint4*)(h16 + (size_t)warp * 256))[lane] = p;

    float ps = h0.x * s0.x + h0.y * s0.y + h0.z * s0.z + h0.w * s0.w +
               h1.x * s1.x + h1.y * s1.y + h1.z * s1.z + h1.w * s1.w;
    float pd = h0.x * d0.x + h0.y * d0.y + h0.z * d0.z + h0.w * d0.w +
               h1.x * d1.x + h1.y * d1.y + h1.z * d1.z + h1.w * d1.w;
#pragma unroll
    for (int o = 4; o >= 1; o >>= 1) {
        ps += __shfl_down_sync(0xffffffffu, ps, o, 8);
        pd += __shfl_down_sync(0xffffffffu, pd, o, 8);
    }
    if ((lane & 7) == 0) {
        int hd = lane >> 3;
        as[warp * 4 + hd] = ps;
        ad[warp * 4 + hd] = pd;
    }
}

__global__ void dots1(const float* __restrict__ h, const float* __restrict__ a_src,
                      const float* __restrict__ a_dst, float* __restrict__ as,
                      float* __restrict__ ad, __half* __restrict__ h16) {
    int warp = (blockIdx.x * blockDim.x + threadIdx.x) >> 5;
    int lane = threadIdx.x & 31;
    if (warp >= N_NODES) return;
    float2 hv = ((const float2*)(h + (size_t)warp * 64))[lane];
    float2 sv = ((const float2*)a_src)[lane];
    float2 dv = ((const float2*)a_dst)[lane];
    ((uint32_t*)(h16 + (size_t)warp * 64))[lane] = pack_h2(hv.x, hv.y);
    float ps = hv.x * sv.x + hv.y * sv.y;
    float pd = hv.x * dv.x + hv.y * dv.y;
#pragma unroll
    for (int o = 16; o >= 1; o >>= 1) {
        ps += __shfl_down_sync(0xffffffffu, ps, o);
        pd += __shfl_down_sync(0xffffffffu, pd, o);
    }
    if (lane == 0) {
        as[warp] = ps;
        ad[warp] = pd;
    }
}

// ---------------- fused GAT layer (softmax + aggregate + bias + relu) -----------
// H=4: one warp per dst node; gathers fp16 messages (512B/row), fp32 accumulate.
__global__ void gat_node4(const __half* __restrict__ h16, const float* __restrict__ as,
                          const float* __restrict__ ad, const int* __restrict__ off,
                          const int* __restrict__ csr_src,
                          const float* __restrict__ bias, float* __restrict__ out) {
    int node = (blockIdx.x * blockDim.x + threadIdx.x) >> 5;
    int lane = threadIdx.x & 31;
    if (node >= N_NODES) return;
    int start = off[node], end = off[node + 1];
    float4 adv = ((const float4*)ad)[node];

    // phase A: warp max of e per head
    float4 mx = make_float4(-INFINITY, -INFINITY, -INFINITY, -INFINITY);
    for (int k = start + lane; k < end; k += 32) {
        int s = __ldg(&csr_src[k]);
        float4 a = __ldg((const float4*)as + s);
        mx.x = fmaxf(mx.x, lrelu(a.x + adv.x));
        mx.y = fmaxf(mx.y, lrelu(a.y + adv.y));
        mx.z = fmaxf(mx.z, lrelu(a.z + adv.z));
        mx.w = fmaxf(mx.w, lrelu(a.w + adv.w));
    }
#pragma unroll
    for (int o = 16; o >= 1; o >>= 1) {
        mx.x = fmaxf(mx.x, __shfl_xor_sync(0xffffffffu, mx.x, o));
        mx.y = fmaxf(mx.y, __shfl_xor_sync(0xffffffffu, mx.y, o));
        mx.z = fmaxf(mx.z, __shfl_xor_sync(0xffffffffu, mx.z, o));
        mx.w = fmaxf(mx.w, __shfl_xor_sync(0xffffffffu, mx.w, o));
    }
    __syncwarp();

    // phase B: per-head numerator / denominator, unrolled x2, fp16 gathers
    int head = lane >> 3;
    float mh = head == 0 ? mx.x : head == 1 ? mx.y : head == 2 ? mx.z : mx.w;
    float advh = head == 0 ? adv.x : head == 1 ? adv.y : head == 2 ? adv.z : adv.w;
    float acc[8] = {};
    float den = 0.0f;
    int k = start;
    for (; k + 2 <= end; k += 2) {
        int s0 = __ldg(&csr_src[k]);
        int s1 = __ldg(&csr_src[k + 1]);
        float as0 = __ldg(&as[s0 * 4 + head]);
        float as1 = __ldg(&as[s1 * 4 + head]);
        uint4 u = ((const uint4*)(h16 + (size_t)s0 * 256))[lane];
        uint4 w = ((const uint4*)(h16 + (size_t)s1 * 256))[lane];
        float ex0 = __expf(lrelu(as0 + advh) - mh);
        float ex1 = __expf(lrelu(as1 + advh) - mh);
        den += ex0 + ex1;
        float2 f;
        f = unpack_h2(u.x); acc[0] += f.x * ex0; acc[1] += f.y * ex0;
        f = unpack_h2(u.y); acc[2] += f.x * ex0; acc[3] += f.y * ex0;
        f = unpack_h2(u.z); acc[4] += f.x * ex0; acc[5] += f.y * ex0;
        f = unpack_h2(u.w); acc[6] += f.x * ex0; acc[7] += f.y * ex0;
        f = unpack_h2(w.x); acc[0] += f.x * ex1; acc[1] += f.y * ex1;
        f = unpack_h2(w.y); acc[2] += f.x * ex1; acc[3] += f.y * ex1;
        f = unpack_h2(w.z); acc[4] += f.x * ex1; acc[5] += f.y * ex1;
        f = unpack_h2(w.w); acc[6] += f.x * ex1; acc[7] += f.y * ex1;
    }
    if (k < end) {
        int s = __ldg(&csr_src[k]);
        float ex = __expf(lrelu(__ldg(&as[s * 4 + head]) + advh) - mh);
        den += ex;
        uint4 u = ((const uint4*)(h16 + (size_t)s * 256))[lane];
        float2 f;
        f = unpack_h2(u.x); acc[0] += f.x * ex; acc[1] += f.y * ex;
        f = unpack_h2(u.y); acc[2] += f.x * ex; acc[3] += f.y * ex;
        f = unpack_h2(u.z); acc[4] += f.x * ex; acc[5] += f.y * ex;
        f = unpack_h2(u.w); acc[6] += f.x * ex; acc[7] += f.y * ex;
    }
    float inv = 1.0f / (den + EPS);
    const float* bp = bias + lane * 8;
    float4 o0, o1;
    o0.x = fmaxf(acc[0] * inv + bp[0], 0.f); o0.y = fmaxf(acc[1] * inv + bp[1], 0.f);
    o0.z = fmaxf(acc[2] * inv + bp[2], 0.f); o0.w = fmaxf(acc[3] * inv + bp[3], 0.f);
    o1.x = fmaxf(acc[4] * inv + bp[4], 0.f); o1.y = fmaxf(acc[5] * inv + bp[5], 0.f);
    o1.z = fmaxf(acc[6] * inv + bp[6], 0.f); o1.w = fmaxf(acc[7] * inv + bp[7], 0.f);
    float4* orow = (float4*)(out + (size_t)node * 256) + lane * 2;
    orow[0] = o0;
    orow[1] = o1;
}

// H=1, C=64 final layer: fused softmax+agg+bias+relu+POOL, fp16 gathers
__global__ void gat_node1_pool(const __half* __restrict__ h16, const float* __restrict__ as,
                               const float* __restrict__ ad, const int* __restrict__ off,
                               const int* __restrict__ csr_src,
                               const float* __restrict__ bias, const int* __restrict__ batch,
                               float* __restrict__ pool) {
    int node = (blockIdx.x * blockDim.x + threadIdx.x) >> 5;
    int lane = threadIdx.x & 31;
    if (node >= N_NODES) return;
    int start = off[node], end = off[node + 1];
    float adv = ad[node];

    float mx = -INFINITY;
    for (int k = start + lane; k < end; k += 32)
        mx = fmaxf(mx, lrelu(__ldg(&as[__ldg(&csr_src[k])]) + adv));
#pragma unroll
    for (int o = 16; o >= 1; o >>= 1)
        mx = fmaxf(mx, __shfl_xor_sync(0xffffffffu, mx, o));
    __syncwarp();

    float acc0 = 0.f, acc1 = 0.f, den = 0.f;
    int k = start;
    for (; k + 2 <= end; k += 2) {
        int s0 = __ldg(&csr_src[k]);
        int s1 = __ldg(&csr_src[k + 1]);
        float a0 = __ldg(&as[s0]);
        float a1 = __ldg(&as[s1]);
        uint32_t u0 = ((const uint32_t*)(h16 + (size_t)s0 * 64))[lane];
        uint32_t u1 = ((const uint32_t*)(h16 + (size_t)s1 * 64))[lane];
        float ex0 = __expf(lrelu(a0 + adv) - mx);
        float ex1 = __expf(lrelu(a1 + adv) - mx);
        den += ex0 + ex1;
        float2 v0 = unpack_h2(u0);
        float2 v1 = unpack_h2(u1);
        acc0 += v0.x * ex0 + v1.x * ex1;
        acc1 += v0.y * ex0 + v1.y * ex1;
    }
    if (k < end) {
        int s = __ldg(&csr_src[k]);
        float ex = __expf(lrelu(__ldg(&as[s]) + adv) - mx);
        den += ex;
        float2 v = unpack_h2(((const uint32_t*)(h16 + (size_t)s * 64))[lane]);
        acc0 += v.x * ex;
        acc1 += v.y * ex;
    }
    float inv = 1.0f / (den + EPS);
    float o0 = fmaxf(acc0 * inv + bias[lane * 2], 0.f);
    float o1 = fmaxf(acc1 * inv + bias[lane * 2 + 1], 0.f);
    int g = batch[node];
    red_add_v2(pool + g * 64 + lane * 2, o0, o1);
    if (lane == 0) atomicAdd(&pool[NG * 64 + g], 1.0f);
}

// ---------------- classifier -----------------------------------------------------
__global__ void classifier(const float* __restrict__ pool, const float* __restrict__ Wl,
                           const float* __restrict__ bl, float* __restrict__ out) {
    int t = threadIdx.x;
    if (t >= NG * NCLS) return;
    int g = t / NCLS, j = t % NCLS;
    float cnt = fmaxf(pool[NG * 64 + g], 1.0f);
    float s = 0.0f;
#pragma unroll
    for (int c = 0; c < 64; c++) s += pool[g * 64 + c] * Wl[c * NCLS + j];
    out[t] = s / cnt + bl[j];
}

// ---------------- launch --------------------------------------------------------
extern "C" void kernel_launch(void* const* d_in, const int* in_sizes, int n_in,
                              void* d_out, int out_size) {
    const float* x   = (const float*)d_in[0];
    const void*  ei  = d_in[1];
    const void*  bat = d_in[2];
    const float* W1 = (const float*)d_in[3];
    const float* s1 = (const float*)d_in[4];
    const float* t1 = (const float*)d_in[5];
    const float* b1 = (const float*)d_in[6];
    const float* W2 = (const float*)d_in[7];
    const float* s2 = (const float*)d_in[8];
    const float* t2 = (const float*)d_in[9];
    const float* b2 = (const float*)d_in[10];
    const float* W3 = (const float*)d_in[11];
    const float* s3 = (const float*)d_in[12];
    const float* t3 = (const float*)d_in[13];
    const float* b3 = (const float*)d_in[14];
    const float* Wl = (const float*)d_in[15];
    const float* bl = (const float*)d_in[16];
    float* out = (float*)d_out;

    float *A, *B, *AS, *AD, *POOL;
    __half* H16;
    int *SRC, *DST, *BATCH, *DEG, *INCL, *BSUM, *OFF, *CUR, *CSR;
    cudaGetSymbolAddress((void**)&A, g_bufA);
    cudaGetSymbolAddress((void**)&B, g_bufB);
    cudaGetSymbolAddress((void**)&H16, g_h16);
    cudaGetSymbolAddress((void**)&AS, g_as);
    cudaGetSymbolAddress((void**)&AD, g_ad);
    cudaGetSymbolAddress((void**)&POOL, g_pool);
    cudaGetSymbolAddress((void**)&SRC, g_src);
    cudaGetSymbolAddress((void**)&DST, g_dst);
    cudaGetSymbolAddress((void**)&BATCH, g_batch);
    cudaGetSymbolAddress((void**)&DEG, g_deg);
    cudaGetSymbolAddress((void**)&INCL, g_incl);
    cudaGetSymbolAddress((void**)&BSUM, g_bsum);
    cudaGetSymbolAddress((void**)&OFF, g_off);
    cudaGetSymbolAddress((void**)&CUR, g_cursor);
    cudaGetSymbolAddress((void**)&CSR, g_csr_src);

    const int TB = 256;
    int eThr = (EE + TB - 1) / TB;
    int nThr = (N_NODES + TB - 1) / TB;
    int nWarp = (N_NODES * 32 + TB - 1) / TB;
    int mT128 = (N_NODES + 127) / 128;

    prep<<<nThr, TB>>>(ei, bat, DEG, POOL);
    build_hist<<<eThr, TB>>>(ei, bat, SRC, DST, DEG, BATCH);
    scan1<<<NB_SCAN, 256>>>(DEG, INCL, BSUM);
    scan2<<<1, 256>>>(BSUM);
    scan3<<<nThr, TB>>>(DEG, INCL, BSUM, OFF, CUR);
    scatter_csr<<<eThr, TB>>>(SRC, DST, CUR, CSR);

    // ---- layer 1: 128 -> 4x64 concat ----
    mma_gemm<128><<<dim3(2, mT128), TB>>>(x, W1, A, N_NODES, 256, 128);
    dots4<<<nWarp, TB>>>(A, s1, t1, AS, AD, H16);
    gat_node4<<<nWarp, TB>>>(H16, AS, AD, OFF, CSR, b1, B);

    // ---- layer 2: 256 -> 4x64 concat ----
    mma_gemm<128><<<dim3(2, mT128), TB>>>(B, W2, A, N_NODES, 256, 256);
    dots4<<<nWarp, TB>>>(A, s2, t2, AS, AD, H16);
    gat_node4<<<nWarp, TB>>>(H16, AS, AD, OFF, CSR, b2, B);

    // ---- layer 3: 256 -> 64, heads=1, no concat; fused with pooling ----
    mma_gemm<64><<<dim3(1, mT128), TB>>>(B, W3, A, N_NODES, 64, 256);
    dots1<<<nWarp, TB>>>(A, s3, t3, AS, AD, H16);
    gat_node1_pool<<<nWarp, TB>>>(H16, AS, AD, OFF, CSR, b3, BATCH, POOL);

    classifier<<<1, 640>>>(POOL, Wl, bl, out);
}

// round 10
// speedup vs baseline: 3.3180x; 1.0796x over previous
#include <cuda_runtime.h>
#include <cuda_fp16.h>
#include <cstdint>

#define N_NODES 50000
#define N_EDGES 800000
#define EE (N_EDGES + N_NODES)   // edges + self loops = 850000
#define NG 64
#define NCLS 10
#define NEG_SLOPE 0.2f
#define EPS 1e-16f
#define NB_SCAN ((N_NODES + 255) / 256)

// ---------------- scratch (static device globals; no runtime alloc) -------------
__device__ __align__(16) float  g_bufB[N_NODES * 256];  // gat output / next gemm input
__device__ __align__(16) __half g_h16[N_NODES * 256];   // fp16 h (written by gemm epilogue)
__device__ __align__(16) float  g_as[N_NODES * 4];
__device__ __align__(16) float  g_ad[N_NODES * 4];
__device__ __align__(16) int    g_src[EE];
__device__ __align__(16) int    g_dst[EE];
__device__ __align__(16) int    g_batch[N_NODES];
__device__ __align__(16) int    g_deg[N_NODES];
__device__ __align__(16) int    g_incl[N_NODES];
__device__ __align__(16) int    g_bsum[256];
__device__ __align__(16) int    g_off[N_NODES + 1];
__device__ __align__(16) int    g_cursor[N_NODES];
__device__ __align__(16) int    g_csr_src[EE];
__device__ __align__(16) float  g_pool[NG * 64 + NG];
__device__ int g_flags[2];

// ---------------- helpers -------------------------------------------------------
__device__ __forceinline__ void red_add_v2(float* addr, float a, float b) {
    asm volatile("red.global.add.v2.f32 [%0], {%1,%2};"
                 :: "l"(addr), "f"(a), "f"(b) : "memory");
}
__device__ __forceinline__ float lrelu(float v) { return v >= 0.0f ? v : NEG_SLOPE * v; }

__device__ __forceinline__ float f2tf32(float x) {
    uint32_t r;
    asm("cvt.rna.tf32.f32 %0, %1;" : "=r"(r) : "f"(x));
    return __uint_as_float(r);
}

__device__ __forceinline__ void mma_tf32(float* d, uint32_t a0, uint32_t a1,
                                         uint32_t a2, uint32_t a3,
                                         uint32_t b0, uint32_t b1) {
    asm("mma.sync.aligned.m16n8k8.row.col.f32.tf32.tf32.f32 "
        "{%0,%1,%2,%3},{%4,%5,%6,%7},{%8,%9},{%0,%1,%2,%3};"
        : "+f"(d[0]), "+f"(d[1]), "+f"(d[2]), "+f"(d[3])
        : "r"(a0), "r"(a1), "r"(a2), "r"(a3), "r"(b0), "r"(b1));
}

__device__ __forceinline__ uint32_t pack_h2(float a, float b) {
    __half2 h = __floats2half2_rn(a, b);
    return *(uint32_t*)&h;
}
__device__ __forceinline__ float2 unpack_h2(uint32_t u) {
    return __half22float2(*(__half2*)&u);
}

// ---------------- prep: dtype detect + zero deg + zero pool ---------------------
__global__ void prep(const void* ei, const void* bat, int* __restrict__ deg,
                     float* __restrict__ pool) {
    int i = blockIdx.x * blockDim.x + threadIdx.x;
    if (i == 0) {
        const long long* e64 = (const long long*)ei;
        int ok = 1;
        for (int j = 0; j < 8; j++) {
            long long v = e64[j];
            if (v < 0 || v >= N_NODES) ok = 0;
        }
        g_flags[0] = ok;
        const long long* b64 = (const long long*)bat;
        int okb = 1;
        for (int j = 0; j < 8; j++) {
            long long v = b64[N_NODES / 2 - 1 - j];
            if (v < 0 || v >= NG) okb = 0;
        }
        g_flags[1] = okb;
    }
    if (i < N_NODES) deg[i] = 0;
    if (i < NG * 64 + NG) pool[i] = 0.0f;
}

__global__ void zero_asad(float* __restrict__ as, float* __restrict__ ad, int n) {
    int i = blockIdx.x * blockDim.x + threadIdx.x;
    if (i < n) { as[i] = 0.0f; ad[i] = 0.0f; }
}

// ---------------- build edges + degree histogram + batch convert ----------------
__global__ void build_hist(const void* ei, const void* bat, int* __restrict__ src,
                           int* __restrict__ dst, int* __restrict__ deg,
                           int* __restrict__ batch) {
    int i = blockIdx.x * blockDim.x + threadIdx.x;
    if (i < EE) {
        int s, d;
        if (i < N_EDGES) {
            if (g_flags[0]) {
                const long long* e = (const long long*)ei;
                s = (int)e[i];
                d = (int)e[N_EDGES + i];
            } else {
                const int* e = (const int*)ei;
                s = e[i];
                d = e[N_EDGES + i];
            }
        } else {
            s = d = i - N_EDGES;
        }
        src[i] = s;
        dst[i] = d;
        atomicAdd(&deg[d], 1);
    }
    if (i < N_NODES) {
        if (g_flags[1]) batch[i] = (int)((const long long*)bat)[i];
        else            batch[i] = ((const int*)bat)[i];
    }
}

// ---------------- CSR scan + scatter --------------------------------------------
__global__ void scan1(const int* __restrict__ deg, int* __restrict__ incl,
                      int* __restrict__ bsum) {
    __shared__ int s[256];
    int t = threadIdx.x;
    int i = blockIdx.x * 256 + t;
    int v = (i < N_NODES) ? deg[i] : 0;
    s[t] = v;
    __syncthreads();
#pragma unroll
    for (int o = 1; o < 256; o <<= 1) {
        int x = (t >= o) ? s[t - o] : 0;
        __syncthreads();
        s[t] += x;
        __syncthreads();
    }
    if (i < N_NODES) incl[i] = s[t];
    if (t == 255) bsum[blockIdx.x] = s[255];
}

__global__ void scan2(int* __restrict__ bsum) {
    __shared__ int s[256];
    int t = threadIdx.x;
    int v = (t < NB_SCAN) ? bsum[t] : 0;
    s[t] = v;
    __syncthreads();
#pragma unroll
    for (int o = 1; o < 256; o <<= 1) {
        int x = (t >= o) ? s[t - o] : 0;
        __syncthreads();
        s[t] += x;
        __syncthreads();
    }
    bsum[t] = s[t] - v;
}

__global__ void scan3(const int* __restrict__ deg, const int* __restrict__ incl,
                      const int* __restrict__ bsum, int* __restrict__ off,
                      int* __restrict__ cursor) {
    int i = blockIdx.x * blockDim.x + threadIdx.x;
    if (i >= N_NODES) return;
    int o = incl[i] - deg[i] + bsum[i >> 8];
    off[i] = o;
    cursor[i] = o;
    if (i == 0) off[N_NODES] = EE;
}

__global__ void scatter_csr(const int* __restrict__ src, const int* __restrict__ dst,
                            int* __restrict__ cursor, int* __restrict__ csr_src) {
    int i = blockIdx.x * blockDim.x + threadIdx.x;
    if (i >= EE) return;
    int pos = atomicAdd(&cursor[dst[i]], 1);
    csr_src[pos] = src[i];
}

// ---------------- TF32 GEMM with fused dots + fp16 emit epilogue -----------------
// h = A@B computed in fp32 accumulators; epilogue emits h16 (fp16) and
// atomically accumulates per-(node,head) a_src/a_dst dot products.
// No fp32 C is ever written. BM=128, BN template, BK=16, 8 warps 2(M)x4(N).
template <int BN>
__global__ void __launch_bounds__(256)
mma_gemm_fused(const float* __restrict__ A, const float* __restrict__ Bm,
               const float* __restrict__ a_src, const float* __restrict__ a_dst,
               float* __restrict__ as, float* __restrict__ ad,
               __half* __restrict__ h16, int M, int N, int K) {
    constexpr int WN = BN / 4;
    constexpr int NT = WN / 8;
    __shared__ float As[16][136];
    __shared__ float Bs[16][BN + 8];
    int tid = threadIdx.x;
    int lane = tid & 31, warp = tid >> 5;
    int wm = (warp & 1) * 64, wn = (warp >> 1) * WN;
    int m0 = blockIdx.y * 128, n0 = blockIdx.x * BN;
    int l3 = lane & 3, l2 = lane >> 2;

    float acc[4][NT][4] = {};

    for (int k0 = 0; k0 < K; k0 += 16) {
#pragma unroll
        for (int i = 0; i < 2; i++) {
            int f = tid * 2 + i;
            int row = f >> 2, c4 = (f & 3) << 2;
            float4 av = make_float4(0.f, 0.f, 0.f, 0.f);
            if (m0 + row < M)
                av = *(const float4*)(A + (size_t)(m0 + row) * K + k0 + c4);
            As[c4 + 0][row] = f2tf32(av.x);
            As[c4 + 1][row] = f2tf32(av.y);
            As[c4 + 2][row] = f2tf32(av.z);
            As[c4 + 3][row] = f2tf32(av.w);
        }
        if (BN == 128) {
#pragma unroll
            for (int i = 0; i < 2; i++) {
                int f = tid * 2 + i;
                int row = f >> 5, c4 = (f & 31) << 2;
                float4 bv = *(const float4*)(Bm + (size_t)(k0 + row) * N + n0 + c4);
                Bs[row][c4 + 0] = f2tf32(bv.x);
                Bs[row][c4 + 1] = f2tf32(bv.y);
                Bs[row][c4 + 2] = f2tf32(bv.z);
                Bs[row][c4 + 3] = f2tf32(bv.w);
            }
        } else {
            int row = tid >> 4, c4 = (tid & 15) << 2;
            float4 bv = *(const float4*)(Bm + (size_t)(k0 + row) * N + n0 + c4);
            Bs[row][c4 + 0] = f2tf32(bv.x);
            Bs[row][c4 + 1] = f2tf32(bv.y);
            Bs[row][c4 + 2] = f2tf32(bv.z);
            Bs[row][c4 + 3] = f2tf32(bv.w);
        }
        __syncthreads();

#pragma unroll
        for (int kk = 0; kk < 16; kk += 8) {
            uint32_t bf[NT][2];
#pragma unroll
            for (int j = 0; j < NT; j++) {
                bf[j][0] = __float_as_uint(Bs[kk + l3][wn + j * 8 + l2]);
                bf[j][1] = __float_as_uint(Bs[kk + l3 + 4][wn + j * 8 + l2]);
            }
#pragma unroll
            for (int i = 0; i < 4; i++) {
                uint32_t a0 = __float_as_uint(As[kk + l3][wm + i * 16 + l2]);
                uint32_t a1 = __float_as_uint(As[kk + l3][wm + i * 16 + l2 + 8]);
                uint32_t a2 = __float_as_uint(As[kk + l3 + 4][wm + i * 16 + l2]);
                uint32_t a3 = __float_as_uint(As[kk + l3 + 4][wm + i * 16 + l2 + 8]);
#pragma unroll
                for (int j = 0; j < NT; j++)
                    mma_tf32(acc[i][j], a0, a1, a2, a3, bf[j][0], bf[j][1]);
            }
        }
        __syncthreads();
    }

    // ---- fused epilogue: h16 emit + per-head attention dot partials ----
    int H = N >> 6;                       // heads (4 or 1)
    int head = (n0 + wn) >> 6;            // warp's columns lie in one head
    float asv[2 * NT], adv[2 * NT];
#pragma unroll
    for (int j = 0; j < NT; j++) {
        int cc = (n0 + wn + j * 8 + 2 * l3) & 63;
        asv[2 * j]     = a_src[head * 64 + cc];
        asv[2 * j + 1] = a_src[head * 64 + cc + 1];
        adv[2 * j]     = a_dst[head * 64 + cc];
        adv[2 * j + 1] = a_dst[head * 64 + cc + 1];
    }
#pragma unroll
    for (int i = 0; i < 4; i++) {
        int r0 = m0 + wm + i * 16 + l2;
        int r1 = r0 + 8;
        float ps0 = 0.f, pd0 = 0.f, ps1 = 0.f, pd1 = 0.f;
#pragma unroll
        for (int j = 0; j < NT; j++) {
            int c = n0 + wn + j * 8 + 2 * l3;
            ps0 += acc[i][j][0] * asv[2 * j] + acc[i][j][1] * asv[2 * j + 1];
            pd0 += acc[i][j][0] * adv[2 * j] + acc[i][j][1] * adv[2 * j + 1];
            ps1 += acc[i][j][2] * asv[2 * j] + acc[i][j][3] * asv[2 * j + 1];
            pd1 += acc[i][j][2] * adv[2 * j] + acc[i][j][3] * adv[2 * j + 1];
            if (r0 < M)
                ((uint32_t*)(h16 + (size_t)r0 * N))[c >> 1] = pack_h2(acc[i][j][0], acc[i][j][1]);
            if (r1 < M)
                ((uint32_t*)(h16 + (size_t)r1 * N))[c >> 1] = pack_h2(acc[i][j][2], acc[i][j][3]);
        }
        // reduce over the 4 lanes (l3 group) sharing the same rows
        ps0 += __shfl_xor_sync(0xffffffffu, ps0, 1);
        ps0 += __shfl_xor_sync(0xffffffffu, ps0, 2);
        pd0 += __shfl_xor_sync(0xffffffffu, pd0, 1);
        pd0 += __shfl_xor_sync(0xffffffffu, pd0, 2);
        ps1 += __shfl_xor_sync(0xffffffffu, ps1, 1);
        ps1 += __shfl_xor_sync(0xffffffffu, ps1, 2);
        pd1 += __shfl_xor_sync(0xffffffffu, pd1, 1);
        pd1 += __shfl_xor_sync(0xffffffffu, pd1, 2);
        if (l3 == 0) {
            if (r0 < M) {
                atomicAdd(&as[r0 * H + head], ps0);
                atomicAdd(&ad[r0 * H + head], pd0);
            }
            if (r1 < M) {
                atomicAdd(&as[r1 * H + head], ps1);
                atomicAdd(&ad[r1 * H + head], pd1);
            }
        }
    }
}

// ---------------- fused GAT layer (softmax + aggregate + bias + relu) -----------
// H=4: one warp per dst node; gathers fp16 messages, fp32 accumulate.
__global__ void gat_node4(const __half* __restrict__ h16, const float* __restrict__ as,
                          const float* __restrict__ ad, const int* __restrict__ off,
                          const int* __restrict__ csr_src,
                          const float* __restrict__ bias, float* __restrict__ out) {
    int node = (blockIdx.x * blockDim.x + threadIdx.x) >> 5;
    int lane = threadIdx.x & 31;
    if (node >= N_NODES) return;
    int start = off[node], end = off[node + 1];
    float4 adv = ((const float4*)ad)[node];

    float4 mx = make_float4(-INFINITY, -INFINITY, -INFINITY, -INFINITY);
    for (int k = start + lane; k < end; k += 32) {
        int s = __ldg(&csr_src[k]);
        float4 a = __ldg((const float4*)as + s);
        mx.x = fmaxf(mx.x, lrelu(a.x + adv.x));
        mx.y = fmaxf(mx.y, lrelu(a.y + adv.y));
        mx.z = fmaxf(mx.z, lrelu(a.z + adv.z));
        mx.w = fmaxf(mx.w, lrelu(a.w + adv.w));
    }
#pragma unroll
    for (int o = 16; o >= 1; o >>= 1) {
        mx.x = fmaxf(mx.x, __shfl_xor_sync(0xffffffffu, mx.x, o));
        mx.y = fmaxf(mx.y, __shfl_xor_sync(0xffffffffu, mx.y, o));
        mx.z = fmaxf(mx.z, __shfl_xor_sync(0xffffffffu, mx.z, o));
        mx.w = fmaxf(mx.w, __shfl_xor_sync(0xffffffffu, mx.w, o));
    }
    __syncwarp();

    int head = lane >> 3;
    float mh = head == 0 ? mx.x : head == 1 ? mx.y : head == 2 ? mx.z : mx.w;
    float advh = head == 0 ? adv.x : head == 1 ? adv.y : head == 2 ? adv.z : adv.w;
    float acc[8] = {};
    float den = 0.0f;
    int k = start;
    for (; k + 2 <= end; k += 2) {
        int s0 = __ldg(&csr_src[k]);
        int s1 = __ldg(&csr_src[k + 1]);
        float as0 = __ldg(&as[s0 * 4 + head]);
        float as1 = __ldg(&as[s1 * 4 + head]);
        uint4 u = ((const uint4*)(h16 + (size_t)s0 * 256))[lane];
        uint4 w = ((const uint4*)(h16 + (size_t)s1 * 256))[lane];
        float ex0 = __expf(lrelu(as0 + advh) - mh);
        float ex1 = __expf(lrelu(as1 + advh) - mh);
        den += ex0 + ex1;
        float2 f;
        f = unpack_h2(u.x); acc[0] += f.x * ex0; acc[1] += f.y * ex0;
        f = unpack_h2(u.y); acc[2] += f.x * ex0; acc[3] += f.y * ex0;
        f = unpack_h2(u.z); acc[4] += f.x * ex0; acc[5] += f.y * ex0;
        f = unpack_h2(u.w); acc[6] += f.x * ex0; acc[7] += f.y * ex0;
        f = unpack_h2(w.x); acc[0] += f.x * ex1; acc[1] += f.y * ex1;
        f = unpack_h2(w.y); acc[2] += f.x * ex1; acc[3] += f.y * ex1;
        f = unpack_h2(w.z); acc[4] += f.x * ex1; acc[5] += f.y * ex1;
        f = unpack_h2(w.w); acc[6] += f.x * ex1; acc[7] += f.y * ex1;
    }
    if (k < end) {
        int s = __ldg(&csr_src[k]);
        float ex = __expf(lrelu(__ldg(&as[s * 4 + head]) + advh) - mh);
        den += ex;
        uint4 u = ((const uint4*)(h16 + (size_t)s * 256))[lane];
        float2 f;
        f = unpack_h2(u.x); acc[0] += f.x * ex; acc[1] += f.y * ex;
        f = unpack_h2(u.y); acc[2] += f.x * ex; acc[3] += f.y * ex;
        f = unpack_h2(u.z); acc[4] += f.x * ex; acc[5] += f.y * ex;
        f = unpack_h2(u.w); acc[6] += f.x * ex; acc[7] += f.y * ex;
    }
    float inv = 1.0f / (den + EPS);
    const float* bp = bias + lane * 8;
    float4 o0, o1;
    o0.x = fmaxf(acc[0] * inv + bp[0], 0.f); o0.y = fmaxf(acc[1] * inv + bp[1], 0.f);
    o0.z = fmaxf(acc[2] * inv + bp[2], 0.f); o0.w = fmaxf(acc[3] * inv + bp[3], 0.f);
    o1.x = fmaxf(acc[4] * inv + bp[4], 0.f); o1.y = fmaxf(acc[5] * inv + bp[5], 0.f);
    o1.z = fmaxf(acc[6] * inv + bp[6], 0.f); o1.w = fmaxf(acc[7] * inv + bp[7], 0.f);
    float4* orow = (float4*)(out + (size_t)node * 256) + lane * 2;
    orow[0] = o0;
    orow[1] = o1;
}

// H=1, C=64 final layer: fused softmax+agg+bias+relu+POOL
__global__ void gat_node1_pool(const __half* __restrict__ h16, const float* __restrict__ as,
                               const float* __restrict__ ad, const int* __restrict__ off,
                               const int* __restrict__ csr_src,
                               const float* __restrict__ bias, const int* __restrict__ batch,
                               float* __restrict__ pool) {
    int node = (blockIdx.x * blockDim.x + threadIdx.x) >> 5;
    int lane = threadIdx.x & 31;
    if (node >= N_NODES) return;
    int start = off[node], end = off[node + 1];
    float adv = ad[node];

    float mx = -INFINITY;
    for (int k = start + lane; k < end; k += 32)
        mx = fmaxf(mx, lrelu(__ldg(&as[__ldg(&csr_src[k])]) + adv));
#pragma unroll
    for (int o = 16; o >= 1; o >>= 1)
        mx = fmaxf(mx, __shfl_xor_sync(0xffffffffu, mx, o));
    __syncwarp();

    float acc0 = 0.f, acc1 = 0.f, den = 0.f;
    int k = start;
    for (; k + 2 <= end; k += 2) {
        int s0 = __ldg(&csr_src[k]);
        int s1 = __ldg(&csr_src[k + 1]);
        float a0 = __ldg(&as[s0]);
        float a1 = __ldg(&as[s1]);
        uint32_t u0 = ((const uint32_t*)(h16 + (size_t)s0 * 64))[lane];
        uint32_t u1 = ((const uint32_t*)(h16 + (size_t)s1 * 64))[lane];
        float ex0 = __expf(lrelu(a0 + adv) - mx);
        float ex1 = __expf(lrelu(a1 + adv) - mx);
        den += ex0 + ex1;
        float2 v0 = unpack_h2(u0);
        float2 v1 = unpack_h2(u1);
        acc0 += v0.x * ex0 + v1.x * ex1;
        acc1 += v0.y * ex0 + v1.y * ex1;
    }
    if (k < end) {
        int s = __ldg(&csr_src[k]);
        float ex = __expf(lrelu(__ldg(&as[s]) + adv) - mx);
        den += ex;
        float2 v = unpack_h2(((const uint32_t*)(h16 + (size_t)s * 64))[lane]);
        acc0 += v.x * ex;
        acc1 += v.y * ex;
    }
    float inv = 1.0f / (den + EPS);
    float o0 = fmaxf(acc0 * inv + bias[lane * 2], 0.f);
    float o1 = fmaxf(acc1 * inv + bias[lane * 2 + 1], 0.f);
    int g = batch[node];
    red_add_v2(pool + g * 64 + lane * 2, o0, o1);
    if (lane == 0) atomicAdd(&pool[NG * 64 + g], 1.0f);
}

// ---------------- classifier -----------------------------------------------------
__global__ void classifier(const float* __restrict__ pool, const float* __restrict__ Wl,
                           const float* __restrict__ bl, float* __restrict__ out) {
    int t = threadIdx.x;
    if (t >= NG * NCLS) return;
    int g = t / NCLS, j = t % NCLS;
    float cnt = fmaxf(pool[NG * 64 + g], 1.0f);
    float s = 0.0f;
#pragma unroll
    for (int c = 0; c < 64; c++) s += pool[g * 64 + c] * Wl[c * NCLS + j];
    out[t] = s / cnt + bl[j];
}

// ---------------- launch --------------------------------------------------------
extern "C" void kernel_launch(void* const* d_in, const int* in_sizes, int n_in,
                              void* d_out, int out_size) {
    const float* x   = (const float*)d_in[0];
    const void*  ei  = d_in[1];
    const void*  bat = d_in[2];
    const float* W1 = (const float*)d_in[3];
    const float* s1 = (const float*)d_in[4];
    const float* t1 = (const float*)d_in[5];
    const float* b1 = (const float*)d_in[6];
    const float* W2 = (const float*)d_in[7];
    const float* s2 = (const float*)d_in[8];
    const float* t2 = (const float*)d_in[9];
    const float* b2 = (const float*)d_in[10];
    const float* W3 = (const float*)d_in[11];
    const float* s3 = (const float*)d_in[12];
    const float* t3 = (const float*)d_in[13];
    const float* b3 = (const float*)d_in[14];
    const float* Wl = (const float*)d_in[15];
    const float* bl = (const float*)d_in[16];
    float* out = (float*)d_out;

    float *B, *AS, *AD, *POOL;
    __half* H16;
    int *SRC, *DST, *BATCH, *DEG, *INCL, *BSUM, *OFF, *CUR, *CSR;
    cudaGetSymbolAddress((void**)&B, g_bufB);
    cudaGetSymbolAddress((void**)&H16, g_h16);
    cudaGetSymbolAddress((void**)&AS, g_as);
    cudaGetSymbolAddress((void**)&AD, g_ad);
    cudaGetSymbolAddress((void**)&POOL, g_pool);
    cudaGetSymbolAddress((void**)&SRC, g_src);
    cudaGetSymbolAddress((void**)&DST, g_dst);
    cudaGetSymbolAddress((void**)&BATCH, g_batch);
    cudaGetSymbolAddress((void**)&DEG, g_deg);
    cudaGetSymbolAddress((void**)&INCL, g_incl);
    cudaGetSymbolAddress((void**)&BSUM, g_bsum);
    cudaGetSymbolAddress((void**)&OFF, g_off);
    cudaGetSymbolAddress((void**)&CUR, g_cursor);
    cudaGetSymbolAddress((void**)&CSR, g_csr_src);

    const int TB = 256;
    int eThr = (EE + TB - 1) / TB;
    int nThr = (N_NODES + TB - 1) / TB;
    int nWarp = (N_NODES * 32 + TB - 1) / TB;
    int mT128 = (N_NODES + 127) / 128;
    int z4 = (N_NODES * 4 + TB - 1) / TB;
    int z1 = nThr;

    prep<<<nThr, TB>>>(ei, bat, DEG, POOL);
    build_hist<<<eThr, TB>>>(ei, bat, SRC, DST, DEG, BATCH);
    scan1<<<NB_SCAN, 256>>>(DEG, INCL, BSUM);
    scan2<<<1, 256>>>(BSUM);
    scan3<<<nThr, TB>>>(DEG, INCL, BSUM, OFF, CUR);
    scatter_csr<<<eThr, TB>>>(SRC, DST, CUR, CSR);

    // ---- layer 1: 128 -> 4x64 concat ----
    zero_asad<<<z4, TB>>>(AS, AD, N_NODES * 4);
    mma_gemm_fused<128><<<dim3(2, mT128), TB>>>(x, W1, s1, t1, AS, AD, H16,
                                                N_NODES, 256, 128);
    gat_node4<<<nWarp, TB>>>(H16, AS, AD, OFF, CSR, b1, B);

    // ---- layer 2: 256 -> 4x64 concat ----
    zero_asad<<<z4, TB>>>(AS, AD, N_NODES * 4);
    mma_gemm_fused<128><<<dim3(2, mT128), TB>>>(B, W2, s2, t2, AS, AD, H16,
                                                N_NODES, 256, 256);
    gat_node4<<<nWarp, TB>>>(H16, AS, AD, OFF, CSR, b2, B);

    // ---- layer 3: 256 -> 64, heads=1, no concat; fused with pooling ----
    zero_asad<<<z1, TB>>>(AS, AD, N_NODES);
    mma_gemm_fused<64><<<dim3(1, mT128), TB>>>(B, W3, s3, t3, AS, AD, H16,
                                               N_NODES, 64, 256);
    gat_node1_pool<<<nWarp, TB>>>(H16, AS, AD, OFF, CSR, b3, BATCH, POOL);

    classifier<<<1, 640>>>(POOL, Wl, bl, out);
}